// round 3
// baseline (speedup 1.0000x reference)
#include <cuda_runtime.h>
#include <math.h>
#include <stdint.h>

#define B_    1024
#define T_    512
#define BT_   (B_*T_)
#define IND   64
#define HD    128
#define G3    384
#define OD    64
#define NEG   0.01f
#define LNEPS 1e-5f

typedef unsigned long long u64;

// ---------------- packed f32x2 helpers ----------------
__device__ __forceinline__ u64 ffma2(u64 a, u64 b, u64 c) {
    u64 d; asm("fma.rn.f32x2 %0, %1, %2, %3;" : "=l"(d) : "l"(a), "l"(b), "l"(c)); return d;
}
__device__ __forceinline__ u64 packdup(float x) {
    u64 r; asm("mov.b64 %0, {%1, %1};" : "=l"(r) : "f"(x)); return r;
}
__device__ __forceinline__ u64 pack2(float x, float y) {
    u64 r; asm("mov.b64 %0, {%1, %2};" : "=l"(r) : "f"(x), "f"(y)); return r;
}
__device__ __forceinline__ float2 unpk(u64 v) {
    float2 f; asm("mov.b64 {%0, %1}, %2;" : "=f"(f.x), "=f"(f.y) : "l"(v)); return f;
}
__device__ __forceinline__ float hsum(u64 v) { float2 f = unpk(v); return f.x + f.y; }

// ---------------- scratch ----------------
static __device__ float g_gates[(size_t)BT_ * G3];   // [B*T, 384]
static __device__ int   g_wordmode;

__global__ void detect_kernel(const unsigned int* __restrict__ p) {
    if (threadIdx.x == 0) {
        int wm = 1;
        for (int i = 0; i < 256; i++) {
            unsigned v = p[i];
            if (v != 0u && v != 1u && v != 0x3F800000u) { wm = 0; break; }
        }
        g_wordmode = wm;
    }
}

// ---------------- FF GEMM (f32x2, acc paired along tokens) ----------------
template<int K>
__device__ inline void gemm_to_smem(const float (*src)[68], const float* __restrict__ W,
                                    const float* __restrict__ bias, float (*dst)[68],
                                    float (*Ws)[68], int tid)
{
    for (int nc = 0; nc < HD; nc += 64) {
        __syncthreads();
        for (int idx = tid; idx < 64 * K; idx += 256) {
            int j = idx / K, k = idx - j * K;
            Ws[k][j] = W[(size_t)nc * K + idx];
        }
        __syncthreads();
        const int tok0 = (tid & 15) << 2, col0 = (tid >> 4) << 2;
        u64 acc[4][2] = {};
        #pragma unroll 4
        for (int k = 0; k < K; k++) {
            double2 ad = *(const double2*)&src[k][tok0];
            u64 a0 = __double_as_longlong(ad.x), a1 = __double_as_longlong(ad.y);
            float4 b = *(const float4*)&Ws[k][col0];
            u64 b0 = packdup(b.x), b1 = packdup(b.y), b2 = packdup(b.z), b3 = packdup(b.w);
            acc[0][0] = ffma2(a0, b0, acc[0][0]); acc[0][1] = ffma2(a1, b0, acc[0][1]);
            acc[1][0] = ffma2(a0, b1, acc[1][0]); acc[1][1] = ffma2(a1, b1, acc[1][1]);
            acc[2][0] = ffma2(a0, b2, acc[2][0]); acc[2][1] = ffma2(a1, b2, acc[2][1]);
            acc[3][0] = ffma2(a0, b3, acc[3][0]); acc[3][1] = ffma2(a1, b3, acc[3][1]);
        }
        #pragma unroll
        for (int ci = 0; ci < 4; ci++) {
            int j = nc + col0 + ci;
            float bb = bias[j];
            float2 lo = unpk(acc[ci][0]), hi = unpk(acc[ci][1]);
            float4 v;
            v.x = lo.x + bb; v.y = lo.y + bb; v.z = hi.x + bb; v.w = hi.y + bb;
            v.x = v.x > 0.f ? v.x : NEG * v.x;
            v.y = v.y > 0.f ? v.y : NEG * v.y;
            v.z = v.z > 0.f ? v.z : NEG * v.z;
            v.w = v.w > 0.f ? v.w : NEG * v.w;
            *(float4*)&dst[j][tok0] = v;
        }
    }
    __syncthreads();
}

__device__ inline void layernorm(float (*buf)[68], const float* __restrict__ gam,
                                 const float* __restrict__ bet, int tid)
{
    int tok = tid >> 2, part = tid & 3;
    float s = 0.f, ss = 0.f;
    #pragma unroll
    for (int i = 0; i < 32; i++) {
        float v = buf[part * 32 + i][tok];
        s += v; ss += v * v;
    }
    s  += __shfl_xor_sync(0xffffffffu, s, 1);  s  += __shfl_xor_sync(0xffffffffu, s, 2);
    ss += __shfl_xor_sync(0xffffffffu, ss, 1); ss += __shfl_xor_sync(0xffffffffu, ss, 2);
    float mu   = s * (1.f / HD);
    float var  = ss * (1.f / HD) - mu * mu;
    float rstd = rsqrtf(var + LNEPS);
    #pragma unroll
    for (int i = 0; i < 32; i++) {
        int j = part * 32 + i;
        float v = buf[j][tok];
        buf[j][tok] = (v - mu) * rstd * gam[j] + bet[j];
    }
    __syncthreads();
}

__device__ inline void gemm3_to_global(const float (*src)[68], const float* __restrict__ W,
                                       const float* __restrict__ bias, float* __restrict__ gout,
                                       float (*Ws)[68], int tid, size_t base)
{
    for (int nc = 0; nc < G3; nc += 64) {
        __syncthreads();
        for (int idx = tid; idx < 64 * HD; idx += 256) {
            int j = idx >> 7, k = idx & 127;
            Ws[k][j] = W[(size_t)nc * HD + idx];
        }
        __syncthreads();
        const int tok0 = (tid & 15) << 2, col0 = (tid >> 4) << 2;
        u64 acc[4][2] = {};
        #pragma unroll 4
        for (int k = 0; k < HD; k++) {
            double2 ad = *(const double2*)&src[k][tok0];
            u64 a0 = __double_as_longlong(ad.x), a1 = __double_as_longlong(ad.y);
            float4 b = *(const float4*)&Ws[k][col0];
            u64 b0 = packdup(b.x), b1 = packdup(b.y), b2 = packdup(b.z), b3 = packdup(b.w);
            acc[0][0] = ffma2(a0, b0, acc[0][0]); acc[0][1] = ffma2(a1, b0, acc[0][1]);
            acc[1][0] = ffma2(a0, b1, acc[1][0]); acc[1][1] = ffma2(a1, b1, acc[1][1]);
            acc[2][0] = ffma2(a0, b2, acc[2][0]); acc[2][1] = ffma2(a1, b2, acc[2][1]);
            acc[3][0] = ffma2(a0, b3, acc[3][0]); acc[3][1] = ffma2(a1, b3, acc[3][1]);
        }
        int col = nc + col0;
        float b0 = bias[col], b1 = bias[col+1], b2 = bias[col+2], b3 = bias[col+3];
        float2 u00 = unpk(acc[0][0]), u01 = unpk(acc[0][1]);
        float2 u10 = unpk(acc[1][0]), u11 = unpk(acc[1][1]);
        float2 u20 = unpk(acc[2][0]), u21 = unpk(acc[2][1]);
        float2 u30 = unpk(acc[3][0]), u31 = unpk(acc[3][1]);
        float4 v;
        v.x = u00.x + b0; v.y = u10.x + b1; v.z = u20.x + b2; v.w = u30.x + b3;
        *(float4*)&gout[(base + tok0 + 0) * G3 + col] = v;
        v.x = u00.y + b0; v.y = u10.y + b1; v.z = u20.y + b2; v.w = u30.y + b3;
        *(float4*)&gout[(base + tok0 + 1) * G3 + col] = v;
        v.x = u01.x + b0; v.y = u11.x + b1; v.z = u21.x + b2; v.w = u31.x + b3;
        *(float4*)&gout[(base + tok0 + 2) * G3 + col] = v;
        v.x = u01.y + b0; v.y = u11.y + b1; v.z = u21.y + b2; v.w = u31.y + b3;
        *(float4*)&gout[(base + tok0 + 3) * G3 + col] = v;
    }
}

// ---------------- FF kernel ----------------
__global__ void __launch_bounds__(256, 2) ff_kernel(
    const float* __restrict__ x,
    const float* __restrict__ W1, const float* __restrict__ b1,
    const float* __restrict__ g1, const float* __restrict__ be1,
    const float* __restrict__ W2, const float* __restrict__ b2,
    const float* __restrict__ g2, const float* __restrict__ be2,
    const float* __restrict__ Wih, const float* __restrict__ bih)
{
    extern __shared__ float sm[];
    float (*A)[68]  = (float(*)[68])sm;
    float (*Bb)[68] = (float(*)[68])(sm + 128 * 68);
    float (*Ws)[68] = (float(*)[68])(sm + 2 * 128 * 68);
    int tid = threadIdx.x;
    size_t base = (size_t)blockIdx.x * 64;

    for (int idx = tid; idx < 64 * IND; idx += 256) {
        int tok = idx >> 6, k = idx & 63;
        A[k][tok] = x[base * IND + idx];
    }
    gemm_to_smem<IND>(A, W1, b1, Bb, Ws, tid);
    layernorm(Bb, g1, be1, tid);
    gemm_to_smem<HD>(Bb, W2, b2, A, Ws, tid);
    layernorm(A, g2, be2, tid);
    gemm3_to_global(A, Wih, bih, g_gates, Ws, tid, base);
}

// ---------------- recurrent kernel (fused out-projection) ----------------
__global__ void __launch_bounds__(512, 1) rec_kernel(
    const float* __restrict__ hx, const float* __restrict__ Whh,
    const float* __restrict__ bhh, const void* __restrict__ isinit,
    const float* __restrict__ Wout, const float* __restrict__ bout,
    float* __restrict__ out, float* __restrict__ hxout)
{
    __shared__ float hs[2][8][HD];
    __shared__ float gx[8][G3];
    __shared__ float ws[OD * HD];     // Wout copy
    __shared__ int initf[8];
    const int tid = threadIdx.x;
    const int r = tid >> 2, c = tid & 3;     // gate GEMM mapping (row r, 32-wide k-chunk c)
    const int oo = tid >> 3, kc = tid & 7;   // out-proj mapping (out col oo, 16-wide k-chunk kc)
    const int b0 = blockIdx.x * 8;

    // register-resident W_hh, packed into f32x2 pairs along K
    u64 w0[16], w1[16], w2[16];
    {
        const float* p0 = Whh + (size_t)r * HD + c * 32;
        const float* p1 = Whh + (size_t)(r + 128) * HD + c * 32;
        const float* p2 = Whh + (size_t)(r + 256) * HD + c * 32;
        #pragma unroll
        for (int i = 0; i < 8; i++) {
            float4 t0 = *(const float4*)(p0 + 4 * i);
            w0[2*i] = pack2(t0.x, t0.y); w0[2*i+1] = pack2(t0.z, t0.w);
            float4 t1 = *(const float4*)(p1 + 4 * i);
            w1[2*i] = pack2(t1.x, t1.y); w1[2*i+1] = pack2(t1.z, t1.w);
            float4 t2 = *(const float4*)(p2 + 4 * i);
            w2[2*i] = pack2(t2.x, t2.y); w2[2*i+1] = pack2(t2.z, t2.w);
        }
    }
    const float bh0 = bhh[r];
    const float bh1 = bhh[r + 128];
    const float bh2 = bhh[r + 256];
    const float bo  = bout[oo];

    for (int idx = tid; idx < OD * HD; idx += 512) ws[idx] = Wout[idx];
    for (int idx = tid; idx < 8 * HD; idx += 512)
        hs[0][idx >> 7][idx & 127] = hx[(size_t)b0 * HD + idx];

    const int wm = g_wordmode;
    const unsigned int*  ii32 = (const unsigned int*)isinit;
    const unsigned char* ii8  = (const unsigned char*)isinit;

    int cur = 0;
    for (int t = 0; t < T_; t++) {
        // stage gates_x (8 x 384), coalesced
        #pragma unroll
        for (int rep = 0; rep < 6; rep++) {
            int flat = rep * 512 + tid;
            int b = flat / G3, j = flat - b * G3;
            gx[b][j] = g_gates[((size_t)(b0 + b) * T_ + t) * G3 + j];
        }
        if (tid < 8) {
            size_t ix = (size_t)(b0 + tid) * T_ + t;
            initf[tid] = wm ? (ii32[ix] != 0u) : (ii8[ix] != 0);
        }
        __syncthreads();

        const int nxt = cur ^ 1;
        #pragma unroll 1
        for (int b = 0; b < 8; b++) {
            u64 a0 = 0ull, a1 = 0ull, a2 = 0ull;
            const int fi = initf[b];
            if (!fi) {
                const double2* hp = (const double2*)&hs[cur][b][c * 32];
                #pragma unroll
                for (int i = 0; i < 8; i++) {
                    double2 hv = hp[i];
                    u64 h0 = __double_as_longlong(hv.x);
                    u64 h1 = __double_as_longlong(hv.y);
                    a0 = ffma2(w0[2*i], h0, a0); a0 = ffma2(w0[2*i+1], h1, a0);
                    a1 = ffma2(w1[2*i], h0, a1); a1 = ffma2(w1[2*i+1], h1, a1);
                    a2 = ffma2(w2[2*i], h0, a2); a2 = ffma2(w2[2*i+1], h1, a2);
                }
            }
            float s0 = hsum(a0), s1 = hsum(a1), s2 = hsum(a2);
            s0 += __shfl_xor_sync(0xffffffffu, s0, 1); s0 += __shfl_xor_sync(0xffffffffu, s0, 2);
            s1 += __shfl_xor_sync(0xffffffffu, s1, 1); s1 += __shfl_xor_sync(0xffffffffu, s1, 2);
            s2 += __shfl_xor_sync(0xffffffffu, s2, 1); s2 += __shfl_xor_sync(0xffffffffu, s2, 2);
            if (c == 0) {
                float hp = fi ? 0.f : hs[cur][b][r];
                float xr = gx[b][r], xz = gx[b][r + 128], xn = gx[b][r + 256];
                float rr = 1.f / (1.f + __expf(-(xr + s0 + bh0)));
                float zz = 1.f / (1.f + __expf(-(xz + s1 + bh1)));
                float nn = tanhf(xn + rr * (s2 + bh2));
                hs[nxt][b][r] = (1.f - zz) * nn + zz * hp;
            }
        }
        __syncthreads();

        // fused output projection: out[b][t][oo] = hs[nxt][b] . Wout[oo] + bout[oo]
        {
            const double2* wp = (const double2*)&ws[oo * HD + kc * 16];
            double2 wv0 = wp[0], wv1 = wp[1], wv2 = wp[2], wv3 = wp[3];
            u64 W0 = __double_as_longlong(wv0.x), W1r = __double_as_longlong(wv0.y);
            u64 W2r = __double_as_longlong(wv1.x), W3 = __double_as_longlong(wv1.y);
            u64 W4 = __double_as_longlong(wv2.x), W5 = __double_as_longlong(wv2.y);
            u64 W6 = __double_as_longlong(wv3.x), W7 = __double_as_longlong(wv3.y);
            #pragma unroll 1
            for (int b = 0; b < 8; b++) {
                const double2* hq = (const double2*)&hs[nxt][b][kc * 16];
                double2 q0 = hq[0], q1 = hq[1], q2 = hq[2], q3 = hq[3];
                u64 acc = ffma2(W0, __double_as_longlong(q0.x), 0ull);
                acc = ffma2(W1r, __double_as_longlong(q0.y), acc);
                acc = ffma2(W2r, __double_as_longlong(q1.x), acc);
                acc = ffma2(W3,  __double_as_longlong(q1.y), acc);
                acc = ffma2(W4,  __double_as_longlong(q2.x), acc);
                acc = ffma2(W5,  __double_as_longlong(q2.y), acc);
                acc = ffma2(W6,  __double_as_longlong(q3.x), acc);
                acc = ffma2(W7,  __double_as_longlong(q3.y), acc);
                float s = hsum(acc);
                s += __shfl_xor_sync(0xffffffffu, s, 1);
                s += __shfl_xor_sync(0xffffffffu, s, 2);
                s += __shfl_xor_sync(0xffffffffu, s, 4);
                if (kc == 0)
                    out[((size_t)(b0 + b) * T_ + t) * OD + oo] = s + bo;
            }
        }
        cur = nxt;
    }
    for (int idx = tid; idx < 8 * HD; idx += 512)
        hxout[(size_t)b0 * HD + idx] = hs[cur][idx >> 7][idx & 127];
}

// ---------------- launcher ----------------
extern "C" void kernel_launch(void* const* d_in, const int* in_sizes, int n_in,
                              void* d_out, int out_size)
{
    const float* x    = (const float*)d_in[0];
    const void*  isin = d_in[1];
    const float* hx   = (const float*)d_in[2];
    const float* W1   = (const float*)d_in[3];
    const float* b1   = (const float*)d_in[4];
    const float* g1   = (const float*)d_in[5];
    const float* be1  = (const float*)d_in[6];
    const float* W2   = (const float*)d_in[7];
    const float* b2   = (const float*)d_in[8];
    const float* g2   = (const float*)d_in[9];
    const float* be2  = (const float*)d_in[10];
    const float* Wih  = (const float*)d_in[11];
    const float* Whh  = (const float*)d_in[12];
    const float* bih  = (const float*)d_in[13];
    const float* bhh  = (const float*)d_in[14];
    const float* Wout = (const float*)d_in[15];
    const float* bout = (const float*)d_in[16];
    float* out = (float*)d_out;

    const int SM_FF = 3 * 128 * 68 * (int)sizeof(float);
    cudaFuncSetAttribute(ff_kernel, cudaFuncAttributeMaxDynamicSharedMemorySize, SM_FF);

    detect_kernel<<<1, 32>>>((const unsigned int*)isin);
    ff_kernel<<<BT_ / 64, 256, SM_FF>>>(x, W1, b1, g1, be1, W2, b2, g2, be2, Wih, bih);
    rec_kernel<<<B_ / 8, 512>>>(hx, Whh, bhh, isin, Wout, bout,
                                out, out + (size_t)BT_ * OD);
}

// round 4
// speedup vs baseline: 1.4793x; 1.4793x over previous
#include <cuda_runtime.h>
#include <math.h>
#include <stdint.h>

#define B_    1024
#define T_    512
#define BT_   (B_*T_)
#define IND   64
#define HD    128
#define G3    384
#define OD    64
#define NEG   0.01f
#define LNEPS 1e-5f
#define PAD   132

// ---------------- scratch ----------------
static __device__ float g_gates[(size_t)BT_ * G3];   // [B*T, 384]
static __device__ float g_y[(size_t)BT_ * HD];       // [B*T, 128]
static __device__ int   g_wordmode;

__global__ void detect_kernel(const unsigned int* __restrict__ p) {
    if (threadIdx.x == 0) {
        int wm = 1;
        for (int i = 0; i < 256; i++) {
            unsigned v = p[i];
            if (v != 0u && v != 1u && v != 0x3F800000u) { wm = 0; break; }
        }
        g_wordmode = wm;
    }
}

// ---------------- 8x8-tile GEMM pieces (ff) ----------------
// S: src [k][tok] (128 tokens), Wb: [k][col] (128 cols), D: dst [col][tok].
// thread (tr,tc) covers tokens tr*8..+7, cols tc*8..+7.
template<int K>
__device__ __forceinline__ void gemm_tile(const float (*S)[PAD], const float (*Wb)[PAD],
                                          const float* __restrict__ bias,
                                          float (*D)[PAD], int tid)
{
    const int tr = tid >> 4, tc = tid & 15;
    const int tok0 = tr * 8, col0 = tc * 8;
    float acc[8][8] = {};
    #pragma unroll 2
    for (int k = 0; k < K; k++) {
        float4 a0 = *(const float4*)&S[k][tok0];
        float4 a1 = *(const float4*)&S[k][tok0 + 4];
        float4 w0 = *(const float4*)&Wb[k][col0];
        float4 w1 = *(const float4*)&Wb[k][col0 + 4];
        float a[8] = {a0.x, a0.y, a0.z, a0.w, a1.x, a1.y, a1.z, a1.w};
        float b[8] = {w0.x, w0.y, w0.z, w0.w, w1.x, w1.y, w1.z, w1.w};
        #pragma unroll
        for (int j = 0; j < 8; j++)
            #pragma unroll
            for (int i = 0; i < 8; i++)
                acc[i][j] = fmaf(a[i], b[j], acc[i][j]);
    }
    #pragma unroll
    for (int j = 0; j < 8; j++) {
        float bv = bias[col0 + j];
        float v[8];
        #pragma unroll
        for (int i = 0; i < 8; i++) {
            float t = acc[i][j] + bv;
            v[i] = t > 0.f ? t : NEG * t;
        }
        *(float4*)&D[col0 + j][tok0]     = make_float4(v[0], v[1], v[2], v[3]);
        *(float4*)&D[col0 + j][tok0 + 4] = make_float4(v[4], v[5], v[6], v[7]);
    }
}

// gates chunk GEMM: write to global [tok][384], cols nc..nc+127, no activation
__device__ __forceinline__ void gemm_gates(const float (*S)[PAD], const float (*Wb)[PAD],
                                           const float* __restrict__ bias,
                                           float* __restrict__ gout,
                                           size_t base, int nc, int tid)
{
    const int tr = tid >> 4, tc = tid & 15;
    const int tok0 = tr * 8, col0 = tc * 8;
    float acc[8][8] = {};
    #pragma unroll 2
    for (int k = 0; k < HD; k++) {
        float4 a0 = *(const float4*)&S[k][tok0];
        float4 a1 = *(const float4*)&S[k][tok0 + 4];
        float4 w0 = *(const float4*)&Wb[k][col0];
        float4 w1 = *(const float4*)&Wb[k][col0 + 4];
        float a[8] = {a0.x, a0.y, a0.z, a0.w, a1.x, a1.y, a1.z, a1.w};
        float b[8] = {w0.x, w0.y, w0.z, w0.w, w1.x, w1.y, w1.z, w1.w};
        #pragma unroll
        for (int j = 0; j < 8; j++)
            #pragma unroll
            for (int i = 0; i < 8; i++)
                acc[i][j] = fmaf(a[i], b[j], acc[i][j]);
    }
    float bb[8];
    #pragma unroll
    for (int j = 0; j < 8; j++) bb[j] = bias[col0 + j];
    #pragma unroll
    for (int i = 0; i < 8; i++) {
        float* row = &gout[(base + tok0 + i) * G3 + nc + col0];
        *(float4*)&row[0] = make_float4(acc[i][0] + bb[0], acc[i][1] + bb[1],
                                        acc[i][2] + bb[2], acc[i][3] + bb[3]);
        *(float4*)&row[4] = make_float4(acc[i][4] + bb[4], acc[i][5] + bb[5],
                                        acc[i][6] + bb[6], acc[i][7] + bb[7]);
    }
}

// LayerNorm over 128 channels, buf [ch][tok], 128 tokens, 256 threads (2/token)
__device__ __forceinline__ void layernorm128(float (*buf)[PAD], const float* __restrict__ gam,
                                             const float* __restrict__ bet, int tid)
{
    const int tok = tid >> 1, part = tid & 1;
    float s = 0.f, ss = 0.f;
    #pragma unroll
    for (int i = 0; i < 64; i++) {
        float v = buf[part * 64 + i][tok];
        s += v; ss += v * v;
    }
    s  += __shfl_xor_sync(0xffffffffu, s, 1);
    ss += __shfl_xor_sync(0xffffffffu, ss, 1);
    float mu   = s * (1.f / HD);
    float var  = ss * (1.f / HD) - mu * mu;
    float rstd = rsqrtf(var + LNEPS);
    #pragma unroll
    for (int i = 0; i < 64; i++) {
        int j = part * 64 + i;
        float v = buf[j][tok];
        buf[j][tok] = (v - mu) * rstd * gam[j] + bet[j];
    }
    __syncthreads();
}

// ---------------- FF kernel: 128 tokens per block ----------------
__global__ void __launch_bounds__(256, 1) ff_kernel(
    const float* __restrict__ x,
    const float* __restrict__ W1, const float* __restrict__ b1,
    const float* __restrict__ g1, const float* __restrict__ be1,
    const float* __restrict__ W2, const float* __restrict__ b2,
    const float* __restrict__ g2, const float* __restrict__ be2,
    const float* __restrict__ Wih, const float* __restrict__ bih)
{
    extern __shared__ float sm[];
    float (*H1)[PAD] = (float(*)[PAD])sm;                    // 128 x PAD
    float (*H2)[PAD] = (float(*)[PAD])(sm + 128 * PAD);      // 128 x PAD (aliases X)
    float (*Wb)[PAD] = (float(*)[PAD])(sm + 256 * PAD);      // 128 x PAD
    const int tid = threadIdx.x;
    const size_t base = (size_t)blockIdx.x * 128;

    // x tile -> H2 region rows 0..63, K-major [k][tok]
    for (int idx = tid; idx < 128 * IND; idx += 256) {
        int tok = idx >> 6, k = idx & 63;
        H2[k][tok] = x[base * IND + idx];
    }
    // W1 [128 out x 64 k] -> Wb[k][j]
    for (int idx = tid; idx < HD * IND; idx += 256) {
        int j = idx >> 6, k = idx & 63;
        Wb[k][j] = W1[idx];
    }
    __syncthreads();
    gemm_tile<IND>(H2, Wb, b1, H1, tid);
    __syncthreads();
    layernorm128(H1, g1, be1, tid);

    // W2 [128 x 128]
    for (int idx = tid; idx < HD * HD; idx += 256) {
        int j = idx >> 7, k = idx & 127;
        Wb[k][j] = W2[idx];
    }
    __syncthreads();
    gemm_tile<HD>(H1, Wb, b2, H2, tid);
    __syncthreads();
    layernorm128(H2, g2, be2, tid);

    // gates: 3 chunks of 128 columns
    for (int nc = 0; nc < G3; nc += 128) {
        __syncthreads();
        for (int idx = tid; idx < HD * HD; idx += 256) {
            int j = idx >> 7, k = idx & 127;
            Wb[k][j] = Wih[(size_t)nc * HD + idx];
        }
        __syncthreads();
        gemm_gates(H2, Wb, bih + nc, g_gates, base, nc, tid);
    }
}

// ---------------- recurrent kernel (R2 structure + gates prefetch) ----------------
__global__ void __launch_bounds__(512, 1) rec_kernel(
    const float* __restrict__ hx, const float* __restrict__ Whh,
    const float* __restrict__ bhh, const void* __restrict__ isinit,
    float* __restrict__ hxout)
{
    __shared__ float hs[2][8][HD];
    __shared__ float gx[8][G3];
    __shared__ int initf[8];
    const int tid = threadIdx.x;
    const int r = tid >> 2, c = tid & 3;           // row r, 32-wide k-chunk c
    const int b0 = blockIdx.x * 8;

    // register-resident W_hh rows r, r+128, r+256, k in [c*32, c*32+32)
    float w0[32], w1[32], w2[32];
    {
        const float* p0 = Whh + (size_t)r * HD + c * 32;
        const float* p1 = Whh + (size_t)(r + 128) * HD + c * 32;
        const float* p2 = Whh + (size_t)(r + 256) * HD + c * 32;
        #pragma unroll
        for (int i = 0; i < 32; i += 4) {
            float4 t0 = *(const float4*)(p0 + i);
            w0[i] = t0.x; w0[i+1] = t0.y; w0[i+2] = t0.z; w0[i+3] = t0.w;
            float4 t1 = *(const float4*)(p1 + i);
            w1[i] = t1.x; w1[i+1] = t1.y; w1[i+2] = t1.z; w1[i+3] = t1.w;
            float4 t2 = *(const float4*)(p2 + i);
            w2[i] = t2.x; w2[i+1] = t2.y; w2[i+2] = t2.z; w2[i+3] = t2.w;
        }
    }
    const float bh0 = (c == 0) ? bhh[r]       : 0.f;
    const float bh1 = (c == 0) ? bhh[r + 128] : 0.f;
    const float bh2 = (c == 0) ? bhh[r + 256] : 0.f;

    for (int idx = tid; idx < 8 * HD; idx += 512)
        hs[0][idx >> 7][idx & 127] = hx[(size_t)b0 * HD + idx];

    const int wm = g_wordmode;
    const unsigned int*  ii32 = (const unsigned int*)isinit;
    const unsigned char* ii8  = (const unsigned char*)isinit;

    // precompute per-rep (b, j) and base pointers for gates staging
    int pb[6], pj[6];
    const float* gp[6];
    #pragma unroll
    for (int rep = 0; rep < 6; rep++) {
        int flat = rep * 512 + tid;
        pb[rep] = flat / G3;
        pj[rep] = flat - pb[rep] * G3;
        gp[rep] = &g_gates[(size_t)(b0 + pb[rep]) * T_ * G3 + pj[rep]];
    }
    const size_t iibase = (size_t)(b0 + tid) * T_;   // valid for tid<8

    // prefetch t=0
    float pf[6];
    #pragma unroll
    for (int rep = 0; rep < 6; rep++) pf[rep] = gp[rep][0];
    int pfin = 0;
    if (tid < 8) pfin = wm ? (ii32[iibase] != 0u) : (ii8[iibase] != 0);

    int cur = 0;
    for (int t = 0; t < T_; t++) {
        #pragma unroll
        for (int rep = 0; rep < 6; rep++) gx[pb[rep]][pj[rep]] = pf[rep];
        if (tid < 8) initf[tid] = pfin;
        __syncthreads();

        // prefetch next step (overlaps compute below)
        if (t + 1 < T_) {
            size_t off = (size_t)(t + 1) * G3;
            #pragma unroll
            for (int rep = 0; rep < 6; rep++) pf[rep] = gp[rep][off];
            if (tid < 8)
                pfin = wm ? (ii32[iibase + t + 1] != 0u) : (ii8[iibase + t + 1] != 0);
        }

        const int nxt = cur ^ 1;
        #pragma unroll 1
        for (int b = 0; b < 8; b++) {
            float a0 = bh0, a1 = bh1, a2 = bh2;
            const int fi = initf[b];
            if (!fi) {
                const float* hp = &hs[cur][b][c * 32];
                #pragma unroll
                for (int i = 0; i < 32; i += 4) {
                    float4 h4 = *(const float4*)(hp + i);
                    a0 = fmaf(w0[i], h4.x, a0); a0 = fmaf(w0[i+1], h4.y, a0);
                    a0 = fmaf(w0[i+2], h4.z, a0); a0 = fmaf(w0[i+3], h4.w, a0);
                    a1 = fmaf(w1[i], h4.x, a1); a1 = fmaf(w1[i+1], h4.y, a1);
                    a1 = fmaf(w1[i+2], h4.z, a1); a1 = fmaf(w1[i+3], h4.w, a1);
                    a2 = fmaf(w2[i], h4.x, a2); a2 = fmaf(w2[i+1], h4.y, a2);
                    a2 = fmaf(w2[i+2], h4.z, a2); a2 = fmaf(w2[i+3], h4.w, a2);
                }
            }
            a0 += __shfl_xor_sync(0xffffffffu, a0, 1); a0 += __shfl_xor_sync(0xffffffffu, a0, 2);
            a1 += __shfl_xor_sync(0xffffffffu, a1, 1); a1 += __shfl_xor_sync(0xffffffffu, a1, 2);
            a2 += __shfl_xor_sync(0xffffffffu, a2, 1); a2 += __shfl_xor_sync(0xffffffffu, a2, 2);
            if (c == 0) {
                float hp = fi ? 0.f : hs[cur][b][r];
                float xr = gx[b][r], xz = gx[b][r + 128], xn = gx[b][r + 256];
                float rr = 1.f / (1.f + __expf(-(xr + a0)));
                float zz = 1.f / (1.f + __expf(-(xz + a1)));
                float nn = tanhf(xn + rr * a2);
                hs[nxt][b][r] = (1.f - zz) * nn + zz * hp;
            }
        }
        __syncthreads();

        // write y for this timestep, coalesced
        #pragma unroll
        for (int rep = 0; rep < 2; rep++) {
            int flat = rep * 512 + tid;
            int b = flat >> 7, k = flat & 127;
            g_y[((size_t)(b0 + b) * T_ + t) * HD + k] = hs[nxt][b][k];
        }
        cur = nxt;
    }
    for (int idx = tid; idx < 8 * HD; idx += 512)
        hxout[(size_t)b0 * HD + idx] = hs[cur][idx >> 7][idx & 127];
}

// ---------------- output projection (R2 version) ----------------
__global__ void __launch_bounds__(256, 2) out_kernel(
    const float* __restrict__ Wout, const float* __restrict__ bout,
    float* __restrict__ out)
{
    extern __shared__ float sm[];
    float (*A)[68]  = (float(*)[68])sm;              // y tile, K-major
    float (*Ws)[68] = (float(*)[68])(sm + 128 * 68); // W_out^T
    int tid = threadIdx.x;
    size_t base = (size_t)blockIdx.x * 64;

    for (int idx = tid; idx < 64 * HD; idx += 256) {
        int tok = idx >> 7, k = idx & 127;
        A[k][tok] = g_y[base * HD + idx];
    }
    for (int idx = tid; idx < OD * HD; idx += 256) {
        int j = idx >> 7, k = idx & 127;
        Ws[k][j] = Wout[idx];
    }
    __syncthreads();

    const int tok0 = (tid & 15) << 2, col0 = (tid >> 4) << 2;
    float acc[4][4] = {};
    #pragma unroll 4
    for (int k = 0; k < HD; k++) {
        float4 a = *(const float4*)&A[k][tok0];
        float4 b = *(const float4*)&Ws[k][col0];
        acc[0][0] += a.x*b.x; acc[0][1] += a.x*b.y; acc[0][2] += a.x*b.z; acc[0][3] += a.x*b.w;
        acc[1][0] += a.y*b.x; acc[1][1] += a.y*b.y; acc[1][2] += a.y*b.z; acc[1][3] += a.y*b.w;
        acc[2][0] += a.z*b.x; acc[2][1] += a.z*b.y; acc[2][2] += a.z*b.z; acc[2][3] += a.z*b.w;
        acc[3][0] += a.w*b.x; acc[3][1] += a.w*b.y; acc[3][2] += a.w*b.z; acc[3][3] += a.w*b.w;
    }
    float b0 = bout[col0], b1 = bout[col0+1], b2 = bout[col0+2], b3 = bout[col0+3];
    #pragma unroll
    for (int ti = 0; ti < 4; ti++) {
        float4 v;
        v.x = acc[ti][0] + b0; v.y = acc[ti][1] + b1;
        v.z = acc[ti][2] + b2; v.w = acc[ti][3] + b3;
        *(float4*)&out[(base + tok0 + ti) * OD + col0] = v;
    }
}

// ---------------- launcher ----------------
extern "C" void kernel_launch(void* const* d_in, const int* in_sizes, int n_in,
                              void* d_out, int out_size)
{
    const float* x    = (const float*)d_in[0];
    const void*  isin = d_in[1];
    const float* hx   = (const float*)d_in[2];
    const float* W1   = (const float*)d_in[3];
    const float* b1   = (const float*)d_in[4];
    const float* g1   = (const float*)d_in[5];
    const float* be1  = (const float*)d_in[6];
    const float* W2   = (const float*)d_in[7];
    const float* b2   = (const float*)d_in[8];
    const float* g2   = (const float*)d_in[9];
    const float* be2  = (const float*)d_in[10];
    const float* Wih  = (const float*)d_in[11];
    const float* Whh  = (const float*)d_in[12];
    const float* bih  = (const float*)d_in[13];
    const float* bhh  = (const float*)d_in[14];
    const float* Wout = (const float*)d_in[15];
    const float* bout = (const float*)d_in[16];
    float* out = (float*)d_out;

    const int SM_FF  = 3 * 128 * PAD * (int)sizeof(float);   // ~198 KB
    const int SM_OUT = 2 * 128 * 68 * (int)sizeof(float);
    cudaFuncSetAttribute(ff_kernel,  cudaFuncAttributeMaxDynamicSharedMemorySize, SM_FF);
    cudaFuncSetAttribute(out_kernel, cudaFuncAttributeMaxDynamicSharedMemorySize, SM_OUT);

    detect_kernel<<<1, 32>>>((const unsigned int*)isin);
    ff_kernel<<<BT_ / 128, 256, SM_FF>>>(x, W1, b1, g1, be1, W2, b2, g2, be2, Wih, bih);
    rec_kernel<<<B_ / 8, 512>>>(hx, Whh, bhh, isin, out + (size_t)BT_ * OD);
    out_kernel<<<BT_ / 64, 256, SM_OUT>>>(Wout, bout, out);
}

// round 6
// speedup vs baseline: 1.9169x; 1.2958x over previous
#include <cuda_runtime.h>
#include <cuda_bf16.h>
#include <math.h>
#include <stdint.h>

#define B_    1024
#define T_    512
#define BT_   (B_*T_)
#define IND   64
#define HD    128
#define G3    384
#define OD    64
#define NEG   0.01f
#define LNEPS 1e-5f

#define ASTR  136              // bf16 elements per smem row (272 B, ldmatrix conflict-free)
#define SSTR  132              // fp32 stage stride

// ---------------- scratch ----------------
static __device__ float g_gates[(size_t)BT_ * G3];   // [B*T, 384]
static __device__ float g_y[(size_t)BT_ * HD];       // [B*T, 128]
static __device__ int   g_wordmode;

__global__ void detect_kernel(const unsigned int* __restrict__ p) {
    if (threadIdx.x == 0) {
        int wm = 1;
        for (int i = 0; i < 256; i++) {
            unsigned v = p[i];
            if (v != 0u && v != 1u && v != 0x3F800000u) { wm = 0; break; }
        }
        g_wordmode = wm;
    }
}

// ---------------- mma.sync helpers ----------------
__device__ __forceinline__ uint32_t smem_u32(const void* p) {
    uint32_t a;
    asm("{ .reg .u64 t; cvta.to.shared.u64 t, %1; cvt.u32.u64 %0, t; }" : "=r"(a) : "l"(p));
    return a;
}
__device__ __forceinline__ void ldsm_x4(uint32_t* r, uint32_t addr) {
    asm volatile("ldmatrix.sync.aligned.m8n8.x4.shared.b16 {%0,%1,%2,%3}, [%4];"
                 : "=r"(r[0]), "=r"(r[1]), "=r"(r[2]), "=r"(r[3]) : "r"(addr));
}
__device__ __forceinline__ void mma16816(float* d, const uint32_t* a, const uint32_t* b) {
    asm volatile("mma.sync.aligned.m16n8k16.row.col.f32.bf16.bf16.f32 "
                 "{%0,%1,%2,%3}, {%4,%5,%6,%7}, {%8,%9}, {%0,%1,%2,%3};"
                 : "+f"(d[0]), "+f"(d[1]), "+f"(d[2]), "+f"(d[3])
                 : "r"(a[0]), "r"(a[1]), "r"(a[2]), "r"(a[3]), "r"(b[0]), "r"(b[1]));
}

// split fp32 pair -> bf16 hi/lo pairs at element offset eo (even)
__device__ __forceinline__ void split2(__nv_bfloat16* hi, __nv_bfloat16* lo, int eo,
                                       float a, float b) {
    __nv_bfloat16 h0 = __float2bfloat16(a), h1 = __float2bfloat16(b);
    __nv_bfloat16 l0 = __float2bfloat16(a - __bfloat162float(h0));
    __nv_bfloat16 l1 = __float2bfloat16(b - __bfloat162float(h1));
    __nv_bfloat162 hh; hh.x = h0; hh.y = h1;
    __nv_bfloat162 ll; ll.x = l0; ll.y = l1;
    *(__nv_bfloat162*)(hi + eo) = hh;
    *(__nv_bfloat162*)(lo + eo) = ll;
}

// weight tile [128 rows][K] fp32 row-major -> smem bf16 hi/lo [row][k], stride ASTR
template<int K>
__device__ __forceinline__ void conv_w(const float* __restrict__ W,
                                       __nv_bfloat16* bh, __nv_bfloat16* bl, int tid) {
    const int total = 128 * (K / 2);
    for (int p = tid; p < total; p += 256) {
        int row = p / (K / 2), kp = p % (K / 2);
        float2 v = *(const float2*)&W[row * K + 2 * kp];
        split2(bh, bl, row * ASTR + 2 * kp, v.x, v.y);
    }
}

// warp GEMM: 16-row strip x 128 cols, 3-product bf16 split, NK k-chunks of 16
template<int NK>
__device__ __forceinline__ void wgemm(uint32_t a_hi, uint32_t a_lo,
                                      uint32_t b_hi, uint32_t b_lo,
                                      float (*acc)[4], int warp, int lane)
{
    const int arow = 16 * warp + (lane & 7) + ((lane & 8) ? 8 : 0);
    const int acg  = (lane & 16) ? 8 : 0;
    const uint32_t aoff = (uint32_t)(arow * ASTR + acg) * 2;
    const int nloc = (lane & 7) + ((lane & 16) ? 8 : 0);
    const int bkg  = (lane & 8) ? 8 : 0;
    const uint32_t boff = (uint32_t)(nloc * ASTR + bkg) * 2;
    #pragma unroll
    for (int k0 = 0; k0 < NK; k0++) {
        uint32_t ah[4], al[4];
        ldsm_x4(ah, a_hi + aoff + k0 * 32);
        ldsm_x4(al, a_lo + aoff + k0 * 32);
        #pragma unroll
        for (int jp = 0; jp < 8; jp++) {
            uint32_t bo = boff + (uint32_t)(jp * 16 * ASTR) * 2 + k0 * 32;
            uint32_t bh[4], bl[4];
            ldsm_x4(bh, b_hi + bo);
            ldsm_x4(bl, b_lo + bo);
            mma16816(acc[2*jp],     ah, bh);
            mma16816(acc[2*jp],     ah, bl);
            mma16816(acc[2*jp],     al, bh);
            mma16816(acc[2*jp + 1], ah, bh + 2);
            mma16816(acc[2*jp + 1], ah, bl + 2);
            mma16816(acc[2*jp + 1], al, bh + 2);
        }
    }
}

// bias + leaky + LayerNorm on fragments; writes bf16-split activations for next phase
__device__ __forceinline__ void ln_epi(float (*acc)[4],
    const float* __restrict__ bias, const float* __restrict__ gam, const float* __restrict__ bet,
    __nv_bfloat16* Ah, __nv_bfloat16* Al, int warp, int lane)
{
    const int r0 = 16 * warp + (lane >> 2), r1 = r0 + 8;
    float s0 = 0.f, q0 = 0.f, s1 = 0.f, q1 = 0.f;
    #pragma unroll
    for (int j = 0; j < 16; j++) {
        int col = 8 * j + 2 * (lane & 3);
        float bv0 = __ldg(&bias[col]), bv1 = __ldg(&bias[col + 1]);
        float v00 = acc[j][0] + bv0; v00 = v00 > 0.f ? v00 : NEG * v00;
        float v01 = acc[j][1] + bv1; v01 = v01 > 0.f ? v01 : NEG * v01;
        float v10 = acc[j][2] + bv0; v10 = v10 > 0.f ? v10 : NEG * v10;
        float v11 = acc[j][3] + bv1; v11 = v11 > 0.f ? v11 : NEG * v11;
        acc[j][0] = v00; acc[j][1] = v01; acc[j][2] = v10; acc[j][3] = v11;
        s0 += v00 + v01; q0 += v00 * v00 + v01 * v01;
        s1 += v10 + v11; q1 += v10 * v10 + v11 * v11;
    }
    s0 += __shfl_xor_sync(0xffffffffu, s0, 1); s0 += __shfl_xor_sync(0xffffffffu, s0, 2);
    q0 += __shfl_xor_sync(0xffffffffu, q0, 1); q0 += __shfl_xor_sync(0xffffffffu, q0, 2);
    s1 += __shfl_xor_sync(0xffffffffu, s1, 1); s1 += __shfl_xor_sync(0xffffffffu, s1, 2);
    q1 += __shfl_xor_sync(0xffffffffu, q1, 1); q1 += __shfl_xor_sync(0xffffffffu, q1, 2);
    float mu0 = s0 * (1.f / 128.f), rs0 = rsqrtf(q0 * (1.f / 128.f) - mu0 * mu0 + LNEPS);
    float mu1 = s1 * (1.f / 128.f), rs1 = rsqrtf(q1 * (1.f / 128.f) - mu1 * mu1 + LNEPS);
    #pragma unroll
    for (int j = 0; j < 16; j++) {
        int col = 8 * j + 2 * (lane & 3);
        float g0 = __ldg(&gam[col]), g1 = __ldg(&gam[col + 1]);
        float t0 = __ldg(&bet[col]), t1 = __ldg(&bet[col + 1]);
        split2(Ah, Al, r0 * ASTR + col,
               (acc[j][0] - mu0) * rs0 * g0 + t0, (acc[j][1] - mu0) * rs0 * g1 + t1);
        split2(Ah, Al, r1 * ASTR + col,
               (acc[j][2] - mu1) * rs1 * g0 + t0, (acc[j][3] - mu1) * rs1 * g1 + t1);
    }
}

// gates: bias add -> fp32 stage (for coalesced global store)
__device__ __forceinline__ void gates_epi(float (*acc)[4], const float* __restrict__ bias,
                                          float* stage, int warp, int lane)
{
    const int r0 = 16 * warp + (lane >> 2), r1 = r0 + 8;
    #pragma unroll
    for (int j = 0; j < 16; j++) {
        int col = 8 * j + 2 * (lane & 3);
        float bv0 = __ldg(&bias[col]), bv1 = __ldg(&bias[col + 1]);
        *(float2*)&stage[r0 * SSTR + col] = make_float2(acc[j][0] + bv0, acc[j][1] + bv1);
        *(float2*)&stage[r1 * SSTR + col] = make_float2(acc[j][2] + bv0, acc[j][3] + bv1);
    }
}

// smem layout (bytes)
#define SM_AH   0
#define SM_AL   (128 * ASTR * 2)
#define SM_BH   (2 * 128 * ASTR * 2)
#define SM_BL   (3 * 128 * ASTR * 2)
#define SM_STG  (4 * 128 * ASTR * 2)
#define SM_TOT  (SM_STG + 128 * SSTR * 4)

// ---------------- FF kernel: HMMA bf16-split, 128 tokens/block ----------------
__global__ void __launch_bounds__(256) ff_kernel(
    const float* __restrict__ x,
    const float* __restrict__ W1, const float* __restrict__ b1,
    const float* __restrict__ g1, const float* __restrict__ be1,
    const float* __restrict__ W2, const float* __restrict__ b2,
    const float* __restrict__ g2, const float* __restrict__ be2,
    const float* __restrict__ Wih, const float* __restrict__ bih)
{
    extern __shared__ char smem[];
    __nv_bfloat16* Ah = (__nv_bfloat16*)(smem + SM_AH);
    __nv_bfloat16* Al = (__nv_bfloat16*)(smem + SM_AL);
    __nv_bfloat16* Bh = (__nv_bfloat16*)(smem + SM_BH);
    __nv_bfloat16* Bl = (__nv_bfloat16*)(smem + SM_BL);
    float* stage = (float*)(smem + SM_STG);
    const uint32_t a_hi = smem_u32(Ah), a_lo = smem_u32(Al);
    const uint32_t b_hi = smem_u32(Bh), b_lo = smem_u32(Bl);
    const int tid = threadIdx.x, warp = tid >> 5, lane = tid & 31;
    const size_t base = (size_t)blockIdx.x * 128;

    // phase 1 inputs: x (split) and W1
    for (int p = tid; p < 128 * 32; p += 256) {
        int row = p >> 5, kp = p & 31;
        float2 v = *(const float2*)&x[(base + row) * IND + 2 * kp];
        split2(Ah, Al, row * ASTR + 2 * kp, v.x, v.y);
    }
    conv_w<IND>(W1, Bh, Bl, tid);
    __syncthreads();

    float acc[16][4];
    #pragma unroll
    for (int j = 0; j < 16; j++) { acc[j][0]=acc[j][1]=acc[j][2]=acc[j][3]=0.f; }
    wgemm<4>(a_hi, a_lo, b_hi, b_lo, acc, warp, lane);
    __syncthreads();
    ln_epi(acc, b1, g1, be1, Ah, Al, warp, lane);

    // phase 2
    conv_w<HD>(W2, Bh, Bl, tid);
    __syncthreads();
    #pragma unroll
    for (int j = 0; j < 16; j++) { acc[j][0]=acc[j][1]=acc[j][2]=acc[j][3]=0.f; }
    wgemm<8>(a_hi, a_lo, b_hi, b_lo, acc, warp, lane);
    __syncthreads();
    ln_epi(acc, b2, g2, be2, Ah, Al, warp, lane);

    // phases 3-5: gates chunks
    for (int c3 = 0; c3 < 3; c3++) {
        conv_w<HD>(Wih + (size_t)c3 * 128 * HD, Bh, Bl, tid);
        __syncthreads();
        #pragma unroll
        for (int j = 0; j < 16; j++) { acc[j][0]=acc[j][1]=acc[j][2]=acc[j][3]=0.f; }
        wgemm<8>(a_hi, a_lo, b_hi, b_lo, acc, warp, lane);
        gates_epi(acc, bih + c3 * 128, stage, warp, lane);
        __syncthreads();
        float* gout = g_gates + base * G3 + c3 * 128;
        for (int it = tid; it < 128 * 128; it += 256) {
            int r = it >> 7, cc = it & 127;
            gout[(size_t)r * G3 + cc] = stage[r * SSTR + cc];
        }
        __syncthreads();
    }
}

// ---------------- recurrent kernel: 148 blocks x <=7 batches ----------------
__global__ void __launch_bounds__(512, 1) rec_kernel(
    const float* __restrict__ hx, const float* __restrict__ Whh,
    const float* __restrict__ bhh, const void* __restrict__ isinit,
    float* __restrict__ hxout)
{
    __shared__ float hs[2][7][HD];
    __shared__ float gx[7][G3];
    __shared__ int initf[8];
    const int tid = threadIdx.x;
    const int r = tid >> 2, c = tid & 3;
    int bstart, bcnt;
    if (blockIdx.x < 136) { bstart = blockIdx.x * 7; bcnt = 7; }
    else                  { bstart = 952 + (blockIdx.x - 136) * 6; bcnt = 6; }

    float w0[32], w1[32], w2[32];
    {
        const float* p0 = Whh + (size_t)r * HD + c * 32;
        const float* p1 = Whh + (size_t)(r + 128) * HD + c * 32;
        const float* p2 = Whh + (size_t)(r + 256) * HD + c * 32;
        #pragma unroll
        for (int i = 0; i < 32; i += 4) {
            float4 t0 = *(const float4*)(p0 + i);
            w0[i] = t0.x; w0[i+1] = t0.y; w0[i+2] = t0.z; w0[i+3] = t0.w;
            float4 t1 = *(const float4*)(p1 + i);
            w1[i] = t1.x; w1[i+1] = t1.y; w1[i+2] = t1.z; w1[i+3] = t1.w;
            float4 t2 = *(const float4*)(p2 + i);
            w2[i] = t2.x; w2[i+1] = t2.y; w2[i+2] = t2.z; w2[i+3] = t2.w;
        }
    }
    const float bh0 = (c == 0) ? bhh[r]       : 0.f;
    const float bh1 = (c == 0) ? bhh[r + 128] : 0.f;
    const float bh2 = (c == 0) ? bhh[r + 256] : 0.f;

    for (int idx = tid; idx < bcnt * HD; idx += 512)
        hs[0][idx >> 7][idx & 127] = hx[(size_t)bstart * HD + idx];

    const int wm = g_wordmode;
    const unsigned int*  ii32 = (const unsigned int*)isinit;
    const unsigned char* ii8  = (const unsigned char*)isinit;

    int pb[6], pj[6], pvalid[6];
    const float* gp[6];
    #pragma unroll
    for (int rep = 0; rep < 6; rep++) {
        int flat = rep * 512 + tid;
        pvalid[rep] = flat < bcnt * G3;
        int b = flat / G3;
        pb[rep] = pvalid[rep] ? b : 0;
        pj[rep] = pvalid[rep] ? (flat - b * G3) : 0;
        gp[rep] = &g_gates[(size_t)(bstart + pb[rep]) * T_ * G3 + pj[rep]];
    }
    const size_t iibase = (size_t)(bstart + tid) * T_;   // tid < bcnt only

    float pf[6];
    #pragma unroll
    for (int rep = 0; rep < 6; rep++) pf[rep] = pvalid[rep] ? gp[rep][0] : 0.f;
    int pfin = 0;
    if (tid < bcnt) pfin = wm ? (ii32[iibase] != 0u) : (ii8[iibase] != 0);

    int cur = 0;
    for (int t = 0; t < T_; t++) {
        #pragma unroll
        for (int rep = 0; rep < 6; rep++)
            if (pvalid[rep]) gx[pb[rep]][pj[rep]] = pf[rep];
        if (tid < bcnt) initf[tid] = pfin;
        __syncthreads();

        if (t + 1 < T_) {
            size_t off = (size_t)(t + 1) * G3;
            #pragma unroll
            for (int rep = 0; rep < 6; rep++)
                if (pvalid[rep]) pf[rep] = gp[rep][off];
            if (tid < bcnt)
                pfin = wm ? (ii32[iibase + t + 1] != 0u) : (ii8[iibase + t + 1] != 0);
        }

        const int nxt = cur ^ 1;
        #pragma unroll 1
        for (int b = 0; b < bcnt; b++) {
            float a0 = bh0, a1 = bh1, a2 = bh2;
            const int fi = initf[b];
            if (!fi) {
                const float* hp = &hs[cur][b][c * 32];
                #pragma unroll
                for (int i = 0; i < 32; i += 4) {
                    float4 h4 = *(const float4*)(hp + i);
                    a0 = fmaf(w0[i], h4.x, a0); a0 = fmaf(w0[i+1], h4.y, a0);
                    a0 = fmaf(w0[i+2], h4.z, a0); a0 = fmaf(w0[i+3], h4.w, a0);
                    a1 = fmaf(w1[i], h4.x, a1); a1 = fmaf(w1[i+1], h4.y, a1);
                    a1 = fmaf(w1[i+2], h4.z, a1); a1 = fmaf(w1[i+3], h4.w, a1);
                    a2 = fmaf(w2[i], h4.x, a2); a2 = fmaf(w2[i+1], h4.y, a2);
                    a2 = fmaf(w2[i+2], h4.z, a2); a2 = fmaf(w2[i+3], h4.w, a2);
                }
            }
            a0 += __shfl_xor_sync(0xffffffffu, a0, 1); a0 += __shfl_xor_sync(0xffffffffu, a0, 2);
            a1 += __shfl_xor_sync(0xffffffffu, a1, 1); a1 += __shfl_xor_sync(0xffffffffu, a1, 2);
            a2 += __shfl_xor_sync(0xffffffffu, a2, 1); a2 += __shfl_xor_sync(0xffffffffu, a2, 2);
            if (c == 0) {
                float hp = fi ? 0.f : hs[cur][b][r];
                float xr = gx[b][r], xz = gx[b][r + 128], xn = gx[b][r + 256];
                float rr = 1.f / (1.f + __expf(-(xr + a0)));
                float zz = 1.f / (1.f + __expf(-(xz + a1)));
                float nn = tanhf(xn + rr * a2);
                hs[nxt][b][r] = (1.f - zz) * nn + zz * hp;
            }
        }
        __syncthreads();

        #pragma unroll
        for (int rep = 0; rep < 2; rep++) {
            int flat = rep * 512 + tid;
            if (flat < bcnt * HD) {
                int b = flat >> 7, k = flat & 127;
                g_y[((size_t)(bstart + b) * T_ + t) * HD + k] = hs[nxt][b][k];
            }
        }
        cur = nxt;
    }
    for (int idx = tid; idx < bcnt * HD; idx += 512)
        hxout[(size_t)bstart * HD + idx] = hs[cur][idx >> 7][idx & 127];
}

// ---------------- output projection ----------------
__global__ void __launch_bounds__(256, 2) out_kernel(
    const float* __restrict__ Wout, const float* __restrict__ bout,
    float* __restrict__ out)
{
    extern __shared__ float sm[];
    float (*A)[68]  = (float(*)[68])sm;
    float (*Ws)[68] = (float(*)[68])(sm + 128 * 68);
    int tid = threadIdx.x;
    size_t base = (size_t)blockIdx.x * 64;

    for (int idx = tid; idx < 64 * HD; idx += 256) {
        int tok = idx >> 7, k = idx & 127;
        A[k][tok] = g_y[base * HD + idx];
    }
    for (int idx = tid; idx < OD * HD; idx += 256) {
        int j = idx >> 7, k = idx & 127;
        Ws[k][j] = Wout[idx];
    }
    __syncthreads();

    const int tok0 = (tid & 15) << 2, col0 = (tid >> 4) << 2;
    float acc[4][4] = {};
    #pragma unroll 4
    for (int k = 0; k < HD; k++) {
        float4 a = *(const float4*)&A[k][tok0];
        float4 b = *(const float4*)&Ws[k][col0];
        acc[0][0] += a.x*b.x; acc[0][1] += a.x*b.y; acc[0][2] += a.x*b.z; acc[0][3] += a.x*b.w;
        acc[1][0] += a.y*b.x; acc[1][1] += a.y*b.y; acc[1][2] += a.y*b.z; acc[1][3] += a.y*b.w;
        acc[2][0] += a.z*b.x; acc[2][1] += a.z*b.y; acc[2][2] += a.z*b.z; acc[2][3] += a.z*b.w;
        acc[3][0] += a.w*b.x; acc[3][1] += a.w*b.y; acc[3][2] += a.w*b.z; acc[3][3] += a.w*b.w;
    }
    float b0 = bout[col0], b1 = bout[col0+1], b2 = bout[col0+2], b3 = bout[col0+3];
    #pragma unroll
    for (int ti = 0; ti < 4; ti++) {
        float4 v;
        v.x = acc[ti][0] + b0; v.y = acc[ti][1] + b1;
        v.z = acc[ti][2] + b2; v.w = acc[ti][3] + b3;
        *(float4*)&out[(base + tok0 + ti) * OD + col0] = v;
    }
}

// ---------------- launcher ----------------
extern "C" void kernel_launch(void* const* d_in, const int* in_sizes, int n_in,
                              void* d_out, int out_size)
{
    const float* x    = (const float*)d_in[0];
    const void*  isin = d_in[1];
    const float* hx   = (const float*)d_in[2];
    const float* W1   = (const float*)d_in[3];
    const float* b1   = (const float*)d_in[4];
    const float* g1   = (const float*)d_in[5];
    const float* be1  = (const float*)d_in[6];
    const float* W2   = (const float*)d_in[7];
    const float* b2   = (const float*)d_in[8];
    const float* g2   = (const float*)d_in[9];
    const float* be2  = (const float*)d_in[10];
    const float* Wih  = (const float*)d_in[11];
    const float* Whh  = (const float*)d_in[12];
    const float* bih  = (const float*)d_in[13];
    const float* bhh  = (const float*)d_in[14];
    const float* Wout = (const float*)d_in[15];
    const float* bout = (const float*)d_in[16];
    float* out = (float*)d_out;

    const int SM_FF  = SM_TOT;                       // ~203 KB
    const int SM_OUT = 2 * 128 * 68 * (int)sizeof(float);
    cudaFuncSetAttribute(ff_kernel,  cudaFuncAttributeMaxDynamicSharedMemorySize, SM_FF);
    cudaFuncSetAttribute(out_kernel, cudaFuncAttributeMaxDynamicSharedMemorySize, SM_OUT);

    detect_kernel<<<1, 32>>>((const unsigned int*)isin);
    ff_kernel<<<BT_ / 128, 256, SM_FF>>>(x, W1, b1, g1, be1, W2, b2, g2, be2, Wih, bih);
    rec_kernel<<<148, 512>>>(hx, Whh, bhh, isin, out + (size_t)BT_ * OD);
    out_kernel<<<BT_ / 64, 256, SM_OUT>>>(Wout, bout, out);
}

// round 7
// speedup vs baseline: 3.2584x; 1.6998x over previous
#include <cuda_runtime.h>
#include <cuda_bf16.h>
#include <math.h>
#include <stdint.h>

#define B_    1024
#define T_    512
#define BT_   (B_*T_)
#define IND   64
#define HD    128
#define G3    384
#define OD    64
#define NEG   0.01f
#define LNEPS 1e-5f

#define ASTR  136              // bf16 elements per smem row in ff (272 B)
#define SSTR  132              // fp32 stage stride in ff

// ---------------- scratch ----------------
static __device__ float g_gates[(size_t)BT_ * G3];   // [B*T, 384]
static __device__ float g_y[(size_t)BT_ * HD];       // [B*T, 128]
static __device__ int   g_wordmode;

__global__ void detect_kernel(const unsigned int* __restrict__ p) {
    if (threadIdx.x == 0) {
        int wm = 1;
        for (int i = 0; i < 256; i++) {
            unsigned v = p[i];
            if (v != 0u && v != 1u && v != 0x3F800000u) { wm = 0; break; }
        }
        g_wordmode = wm;
    }
}

// ---------------- mma.sync helpers ----------------
__device__ __forceinline__ uint32_t smem_u32(const void* p) {
    uint32_t a;
    asm("{ .reg .u64 t; cvta.to.shared.u64 t, %1; cvt.u32.u64 %0, t; }" : "=r"(a) : "l"(p));
    return a;
}
__device__ __forceinline__ void ldsm_x4(uint32_t* r, uint32_t addr) {
    asm volatile("ldmatrix.sync.aligned.m8n8.x4.shared.b16 {%0,%1,%2,%3}, [%4];"
                 : "=r"(r[0]), "=r"(r[1]), "=r"(r[2]), "=r"(r[3]) : "r"(addr));
}
__device__ __forceinline__ void mma16816(float* d, const uint32_t* a, const uint32_t* b) {
    asm volatile("mma.sync.aligned.m16n8k16.row.col.f32.bf16.bf16.f32 "
                 "{%0,%1,%2,%3}, {%4,%5,%6,%7}, {%8,%9}, {%0,%1,%2,%3};"
                 : "+f"(d[0]), "+f"(d[1]), "+f"(d[2]), "+f"(d[3])
                 : "r"(a[0]), "r"(a[1]), "r"(a[2]), "r"(a[3]), "r"(b[0]), "r"(b[1]));
}

// split fp32 pair -> bf16 hi/lo pairs at element offset eo (even) [ff layout]
__device__ __forceinline__ void split2(__nv_bfloat16* hi, __nv_bfloat16* lo, int eo,
                                       float a, float b) {
    __nv_bfloat16 h0 = __float2bfloat16(a), h1 = __float2bfloat16(b);
    __nv_bfloat16 l0 = __float2bfloat16(a - __bfloat162float(h0));
    __nv_bfloat16 l1 = __float2bfloat16(b - __bfloat162float(h1));
    __nv_bfloat162 hh; hh.x = h0; hh.y = h1;
    __nv_bfloat162 ll; ll.x = l0; ll.y = l1;
    *(__nv_bfloat162*)(hi + eo) = hh;
    *(__nv_bfloat162*)(lo + eo) = ll;
}

// ============================== FF (unchanged, R6) ==============================
template<int K>
__device__ __forceinline__ void conv_w(const float* __restrict__ W,
                                       __nv_bfloat16* bh, __nv_bfloat16* bl, int tid) {
    const int total = 128 * (K / 2);
    for (int p = tid; p < total; p += 256) {
        int row = p / (K / 2), kp = p % (K / 2);
        float2 v = *(const float2*)&W[row * K + 2 * kp];
        split2(bh, bl, row * ASTR + 2 * kp, v.x, v.y);
    }
}

template<int NK>
__device__ __forceinline__ void wgemm(uint32_t a_hi, uint32_t a_lo,
                                      uint32_t b_hi, uint32_t b_lo,
                                      float (*acc)[4], int warp, int lane)
{
    const int arow = 16 * warp + (lane & 7) + ((lane & 8) ? 8 : 0);
    const int acg  = (lane & 16) ? 8 : 0;
    const uint32_t aoff = (uint32_t)(arow * ASTR + acg) * 2;
    const int nloc = (lane & 7) + ((lane & 16) ? 8 : 0);
    const int bkg  = (lane & 8) ? 8 : 0;
    const uint32_t boff = (uint32_t)(nloc * ASTR + bkg) * 2;
    #pragma unroll
    for (int k0 = 0; k0 < NK; k0++) {
        uint32_t ah[4], al[4];
        ldsm_x4(ah, a_hi + aoff + k0 * 32);
        ldsm_x4(al, a_lo + aoff + k0 * 32);
        #pragma unroll
        for (int jp = 0; jp < 8; jp++) {
            uint32_t bo = boff + (uint32_t)(jp * 16 * ASTR) * 2 + k0 * 32;
            uint32_t bh[4], bl[4];
            ldsm_x4(bh, b_hi + bo);
            ldsm_x4(bl, b_lo + bo);
            mma16816(acc[2*jp],     ah, bh);
            mma16816(acc[2*jp],     ah, bl);
            mma16816(acc[2*jp],     al, bh);
            mma16816(acc[2*jp + 1], ah, bh + 2);
            mma16816(acc[2*jp + 1], ah, bl + 2);
            mma16816(acc[2*jp + 1], al, bh + 2);
        }
    }
}

__device__ __forceinline__ void ln_epi(float (*acc)[4],
    const float* __restrict__ bias, const float* __restrict__ gam, const float* __restrict__ bet,
    __nv_bfloat16* Ah, __nv_bfloat16* Al, int warp, int lane)
{
    const int r0 = 16 * warp + (lane >> 2), r1 = r0 + 8;
    float s0 = 0.f, q0 = 0.f, s1 = 0.f, q1 = 0.f;
    #pragma unroll
    for (int j = 0; j < 16; j++) {
        int col = 8 * j + 2 * (lane & 3);
        float bv0 = __ldg(&bias[col]), bv1 = __ldg(&bias[col + 1]);
        float v00 = acc[j][0] + bv0; v00 = v00 > 0.f ? v00 : NEG * v00;
        float v01 = acc[j][1] + bv1; v01 = v01 > 0.f ? v01 : NEG * v01;
        float v10 = acc[j][2] + bv0; v10 = v10 > 0.f ? v10 : NEG * v10;
        float v11 = acc[j][3] + bv1; v11 = v11 > 0.f ? v11 : NEG * v11;
        acc[j][0] = v00; acc[j][1] = v01; acc[j][2] = v10; acc[j][3] = v11;
        s0 += v00 + v01; q0 += v00 * v00 + v01 * v01;
        s1 += v10 + v11; q1 += v10 * v10 + v11 * v11;
    }
    s0 += __shfl_xor_sync(0xffffffffu, s0, 1); s0 += __shfl_xor_sync(0xffffffffu, s0, 2);
    q0 += __shfl_xor_sync(0xffffffffu, q0, 1); q0 += __shfl_xor_sync(0xffffffffu, q0, 2);
    s1 += __shfl_xor_sync(0xffffffffu, s1, 1); s1 += __shfl_xor_sync(0xffffffffu, s1, 2);
    q1 += __shfl_xor_sync(0xffffffffu, q1, 1); q1 += __shfl_xor_sync(0xffffffffu, q1, 2);
    float mu0 = s0 * (1.f / 128.f), rs0 = rsqrtf(q0 * (1.f / 128.f) - mu0 * mu0 + LNEPS);
    float mu1 = s1 * (1.f / 128.f), rs1 = rsqrtf(q1 * (1.f / 128.f) - mu1 * mu1 + LNEPS);
    #pragma unroll
    for (int j = 0; j < 16; j++) {
        int col = 8 * j + 2 * (lane & 3);
        float g0 = __ldg(&gam[col]), g1 = __ldg(&gam[col + 1]);
        float t0 = __ldg(&bet[col]), t1 = __ldg(&bet[col + 1]);
        split2(Ah, Al, r0 * ASTR + col,
               (acc[j][0] - mu0) * rs0 * g0 + t0, (acc[j][1] - mu0) * rs0 * g1 + t1);
        split2(Ah, Al, r1 * ASTR + col,
               (acc[j][2] - mu1) * rs1 * g0 + t0, (acc[j][3] - mu1) * rs1 * g1 + t1);
    }
}

__device__ __forceinline__ void gates_epi(float (*acc)[4], const float* __restrict__ bias,
                                          float* stage, int warp, int lane)
{
    const int r0 = 16 * warp + (lane >> 2), r1 = r0 + 8;
    #pragma unroll
    for (int j = 0; j < 16; j++) {
        int col = 8 * j + 2 * (lane & 3);
        float bv0 = __ldg(&bias[col]), bv1 = __ldg(&bias[col + 1]);
        *(float2*)&stage[r0 * SSTR + col] = make_float2(acc[j][0] + bv0, acc[j][1] + bv1);
        *(float2*)&stage[r1 * SSTR + col] = make_float2(acc[j][2] + bv0, acc[j][3] + bv1);
    }
}

#define SM_AH   0
#define SM_AL   (128 * ASTR * 2)
#define SM_BH   (2 * 128 * ASTR * 2)
#define SM_BL   (3 * 128 * ASTR * 2)
#define SM_STG  (4 * 128 * ASTR * 2)
#define SM_TOT  (SM_STG + 128 * SSTR * 4)

__global__ void __launch_bounds__(256) ff_kernel(
    const float* __restrict__ x,
    const float* __restrict__ W1, const float* __restrict__ b1,
    const float* __restrict__ g1, const float* __restrict__ be1,
    const float* __restrict__ W2, const float* __restrict__ b2,
    const float* __restrict__ g2, const float* __restrict__ be2,
    const float* __restrict__ Wih, const float* __restrict__ bih)
{
    extern __shared__ char smem[];
    __nv_bfloat16* Ah = (__nv_bfloat16*)(smem + SM_AH);
    __nv_bfloat16* Al = (__nv_bfloat16*)(smem + SM_AL);
    __nv_bfloat16* Bh = (__nv_bfloat16*)(smem + SM_BH);
    __nv_bfloat16* Bl = (__nv_bfloat16*)(smem + SM_BL);
    float* stage = (float*)(smem + SM_STG);
    const uint32_t a_hi = smem_u32(Ah), a_lo = smem_u32(Al);
    const uint32_t b_hi = smem_u32(Bh), b_lo = smem_u32(Bl);
    const int tid = threadIdx.x, warp = tid >> 5, lane = tid & 31;
    const size_t base = (size_t)blockIdx.x * 128;

    for (int p = tid; p < 128 * 32; p += 256) {
        int row = p >> 5, kp = p & 31;
        float2 v = *(const float2*)&x[(base + row) * IND + 2 * kp];
        split2(Ah, Al, row * ASTR + 2 * kp, v.x, v.y);
    }
    conv_w<IND>(W1, Bh, Bl, tid);
    __syncthreads();

    float acc[16][4];
    #pragma unroll
    for (int j = 0; j < 16; j++) { acc[j][0]=acc[j][1]=acc[j][2]=acc[j][3]=0.f; }
    wgemm<4>(a_hi, a_lo, b_hi, b_lo, acc, warp, lane);
    __syncthreads();
    ln_epi(acc, b1, g1, be1, Ah, Al, warp, lane);

    conv_w<HD>(W2, Bh, Bl, tid);
    __syncthreads();
    #pragma unroll
    for (int j = 0; j < 16; j++) { acc[j][0]=acc[j][1]=acc[j][2]=acc[j][3]=0.f; }
    wgemm<8>(a_hi, a_lo, b_hi, b_lo, acc, warp, lane);
    __syncthreads();
    ln_epi(acc, b2, g2, be2, Ah, Al, warp, lane);

    for (int c3 = 0; c3 < 3; c3++) {
        conv_w<HD>(Wih + (size_t)c3 * 128 * HD, Bh, Bl, tid);
        __syncthreads();
        #pragma unroll
        for (int j = 0; j < 16; j++) { acc[j][0]=acc[j][1]=acc[j][2]=acc[j][3]=0.f; }
        wgemm<8>(a_hi, a_lo, b_hi, b_lo, acc, warp, lane);
        gates_epi(acc, bih + c3 * 128, stage, warp, lane);
        __syncthreads();
        float* gout = g_gates + base * G3 + c3 * 128;
        for (int it = tid; it < 128 * 128; it += 256) {
            int r = it >> 7, cc = it & 127;
            gout[(size_t)r * G3 + cc] = stage[r * SSTR + cc];
        }
        __syncthreads();
    }
}

// ============================== REC (HMMA rewrite) ==============================
// smem layout (bytes): W hi/lo [384 cols][128 k] bf16 swizzled 256B rows;
// A hi/lo [16 batch][128 k]; GH fp32 [16][388]
#define RSM_WH  0
#define RSM_WL  98304
#define RSM_AH  196608
#define RSM_AL  200704
#define RSM_GH  204800
#define RSM_TOT (RSM_GH + 16 * 388 * 4)   // 229632 <= 232448

__device__ __forceinline__ float sigf(float x) {
    float e = __expf(-x);
    return __fdividef(1.f, 1.f + e);
}
__device__ __forceinline__ float tanhf_fast(float x) {
    return fmaf(2.f, sigf(2.f * x), -1.f);
}

// store 4 consecutive (even-aligned) elems of batch b at j0 (mult of 4) into swizzled A
__device__ __forceinline__ void stA(char* AH, char* AL, int b, int j0, float4 h) {
    uint32_t off = (uint32_t)(b * 256 + (((j0 >> 3) ^ (b & 7)) << 4) + (j0 & 7) * 2);
    split2((__nv_bfloat16*)(AH + off), (__nv_bfloat16*)(AL + off), 0, h.x, h.y);
    split2((__nv_bfloat16*)(AH + off + 4), (__nv_bfloat16*)(AL + off + 4), 0, h.z, h.w);
}
// load hi+lo reconstruction of 4 elems
__device__ __forceinline__ float4 ldA(const char* AH, const char* AL, int b, int j0) {
    uint32_t off = (uint32_t)(b * 256 + (((j0 >> 3) ^ (b & 7)) << 4) + (j0 & 7) * 2);
    uint2 hu = *(const uint2*)(AH + off);
    uint2 lu = *(const uint2*)(AL + off);
    float2 h0 = __bfloat1622float2(*(__nv_bfloat162*)&hu.x);
    float2 h1 = __bfloat1622float2(*(__nv_bfloat162*)&hu.y);
    float2 l0 = __bfloat1622float2(*(__nv_bfloat162*)&lu.x);
    float2 l1 = __bfloat1622float2(*(__nv_bfloat162*)&lu.y);
    return make_float4(h0.x + l0.x, h0.y + l0.y, h1.x + l1.x, h1.y + l1.y);
}

__global__ void __launch_bounds__(256, 1) rec_kernel(
    const float* __restrict__ hx, const float* __restrict__ Whh,
    const float* __restrict__ bhh, const void* __restrict__ isinit,
    float* __restrict__ hxout)
{
    extern __shared__ char sm[];
    char* WH = sm + RSM_WH;
    char* WL = sm + RSM_WL;
    char* AH = sm + RSM_AH;
    char* AL = sm + RSM_AL;
    float* GH = (float*)(sm + RSM_GH);
    const uint32_t whb = smem_u32(WH), wlb = smem_u32(WL);
    const uint32_t ahb = smem_u32(AH), alb = smem_u32(AL);
    const int tid = threadIdx.x, warp = tid >> 5, lane = tid & 31;
    const int b0 = blockIdx.x * 16;

    // ---- prologue: convert W_hh to bf16 hi/lo, swizzled [col][k] 256B rows ----
    for (int p = tid; p < 384 * 64; p += 256) {
        int row = p >> 6, kp = p & 63, k = kp * 2;
        float2 v = *(const float2*)&Whh[row * 128 + k];
        uint32_t off = (uint32_t)(row * 256 + (((k >> 3) ^ (row & 7)) << 4) + (k & 7) * 2);
        split2((__nv_bfloat16*)(WH + off), (__nv_bfloat16*)(WL + off), 0, v.x, v.y);
    }

    // per-warp bias fragments (6 n8-tiles)
    float bv[6][2];
    #pragma unroll
    for (int a = 0; a < 6; a++) {
        int col = 48 * warp + 8 * a + 2 * (lane & 3);
        bv[a][0] = __ldg(&bhh[col]);
        bv[a][1] = __ldg(&bhh[col + 1]);
    }

    const int wm = g_wordmode;
    const unsigned int*  ii32 = (const unsigned int*)isinit;
    const unsigned char* ii8  = (const unsigned char*)isinit;

    // epilogue mapping: thread owns (b in {warp, warp+8}, j0 = 4*lane)
    const int j0 = 4 * lane;
    int bb[2]; bb[0] = warp; bb[1] = warp + 8;

    // build A for t=0 from hx (zeroed per is_init[t=0]); prefetch gx t=0
    float4 gxr[2][3];
    #pragma unroll
    for (int bi = 0; bi < 2; bi++) {
        int b = bb[bi];
        size_t ib = (size_t)(b0 + b) * T_;
        int f0 = wm ? (ii32[ib] != 0u) : (ii8[ib] != 0);
        float4 h4 = *(const float4*)&hx[(size_t)(b0 + b) * HD + j0];
        if (f0) h4 = make_float4(0.f, 0.f, 0.f, 0.f);
        stA(AH, AL, b, j0, h4);
        #pragma unroll
        for (int g = 0; g < 3; g++)
            gxr[bi][g] = *(const float4*)&g_gates[ib * G3 + g * 128 + j0];
    }

    // ldmatrix address components (constant across steps)
    const int arow = lane & 15;
    const uint32_t abase = (uint32_t)(arow * 256);
    const int achx = (lane & 16) ? 1 : 0, arx = arow & 7;
    const int nbs = 48 * warp + (lane & 7) + ((lane & 16) ? 8 : 0);
    const int bchx = (lane & 8) ? 1 : 0;

    for (int t = 0; t < T_; t++) {
        __syncthreads();   // A(t) ready; GH(t-1) consumed

        // prefetch next step's gx + init flags (overlaps MMA)
        float4 ngx[2][3];
        int nf[2]; nf[0] = 0; nf[1] = 0;
        if (t + 1 < T_) {
            #pragma unroll
            for (int bi = 0; bi < 2; bi++) {
                size_t ib = (size_t)(b0 + bb[bi]) * T_ + (t + 1);
                nf[bi] = wm ? (ii32[ib] != 0u) : (ii8[ib] != 0);
                #pragma unroll
                for (int g = 0; g < 3; g++)
                    ngx[bi][g] = *(const float4*)&g_gates[ib * G3 + g * 128 + j0];
            }
        }

        // ---- MMA: gh = h @ W_hh^T + b_hh (3-product bf16 split) ----
        float acc[6][4];
        #pragma unroll
        for (int a = 0; a < 6; a++) {
            acc[a][0] = bv[a][0]; acc[a][1] = bv[a][1];
            acc[a][2] = bv[a][0]; acc[a][3] = bv[a][1];
        }
        #pragma unroll
        for (int k0 = 0; k0 < 8; k0++) {
            uint32_t ach = (uint32_t)((2 * k0 + achx) ^ arx);
            uint32_t ah4[4], al4[4];
            ldsm_x4(ah4, ahb + abase + (ach << 4));
            ldsm_x4(al4, alb + abase + (ach << 4));
            #pragma unroll
            for (int jj = 0; jj < 3; jj++) {
                int n = nbs + 16 * jj;
                uint32_t bch = (uint32_t)((2 * k0 + bchx) ^ (n & 7));
                uint32_t boff = (uint32_t)(n * 256) + (bch << 4);
                uint32_t bh4[4], bl4[4];
                ldsm_x4(bh4, whb + boff);
                ldsm_x4(bl4, wlb + boff);
                mma16816(acc[2*jj],     ah4, bh4);
                mma16816(acc[2*jj],     ah4, bl4);
                mma16816(acc[2*jj],     al4, bh4);
                mma16816(acc[2*jj + 1], ah4, bh4 + 2);
                mma16816(acc[2*jj + 1], ah4, bl4 + 2);
                mma16816(acc[2*jj + 1], al4, bh4 + 2);
            }
        }

        // ---- dump gh fragments to stage ----
        {
            const int r0 = lane >> 2, r1 = r0 + 8;
            #pragma unroll
            for (int a = 0; a < 6; a++) {
                int col = 48 * warp + 8 * a + 2 * (lane & 3);
                *(float2*)&GH[r0 * 388 + col] = make_float2(acc[a][0], acc[a][1]);
                *(float2*)&GH[r1 * 388 + col] = make_float2(acc[a][2], acc[a][3]);
            }
        }
        __syncthreads();   // gh visible

        // ---- epilogue: GRU nonlinearity, y store, next-A build ----
        #pragma unroll
        for (int bi = 0; bi < 2; bi++) {
            int b = bb[bi];
            float4 hr = *(const float4*)&GH[b * 388 + j0];
            float4 hz = *(const float4*)&GH[b * 388 + 128 + j0];
            float4 hn = *(const float4*)&GH[b * 388 + 256 + j0];
            float4 hp = ldA(AH, AL, b, j0);
            float4 xr = gxr[bi][0], xz = gxr[bi][1], xn = gxr[bi][2];
            float4 hnew;
            {
                float r, z, n;
                r = sigf(xr.x + hr.x); z = sigf(xz.x + hz.x);
                n = tanhf_fast(xn.x + r * hn.x); hnew.x = (1.f - z) * n + z * hp.x;
                r = sigf(xr.y + hr.y); z = sigf(xz.y + hz.y);
                n = tanhf_fast(xn.y + r * hn.y); hnew.y = (1.f - z) * n + z * hp.y;
                r = sigf(xr.z + hr.z); z = sigf(xz.z + hz.z);
                n = tanhf_fast(xn.z + r * hn.z); hnew.z = (1.f - z) * n + z * hp.z;
                r = sigf(xr.w + hr.w); z = sigf(xz.w + hz.w);
                n = tanhf_fast(xn.w + r * hn.w); hnew.w = (1.f - z) * n + z * hp.w;
            }
            *(float4*)&g_y[((size_t)(b0 + b) * T_ + t) * HD + j0] = hnew;
            if (t + 1 < T_) {
                float4 he = nf[bi] ? make_float4(0.f, 0.f, 0.f, 0.f) : hnew;
                stA(AH, AL, b, j0, he);
            } else {
                *(float4*)&hxout[(size_t)(b0 + b) * HD + j0] = hnew;
            }
        }
        if (t + 1 < T_) {
            #pragma unroll
            for (int bi = 0; bi < 2; bi++)
                #pragma unroll
                for (int g = 0; g < 3; g++)
                    gxr[bi][g] = ngx[bi][g];
        }
    }
}

// ---------------- output projection ----------------
__global__ void __launch_bounds__(256, 2) out_kernel(
    const float* __restrict__ Wout, const float* __restrict__ bout,
    float* __restrict__ out)
{
    extern __shared__ float smf[];
    float (*A)[68]  = (float(*)[68])smf;
    float (*Ws)[68] = (float(*)[68])(smf + 128 * 68);
    int tid = threadIdx.x;
    size_t base = (size_t)blockIdx.x * 64;

    for (int idx = tid; idx < 64 * HD; idx += 256) {
        int tok = idx >> 7, k = idx & 127;
        A[k][tok] = g_y[base * HD + idx];
    }
    for (int idx = tid; idx < OD * HD; idx += 256) {
        int j = idx >> 7, k = idx & 127;
        Ws[k][j] = Wout[idx];
    }
    __syncthreads();

    const int tok0 = (tid & 15) << 2, col0 = (tid >> 4) << 2;
    float acc[4][4] = {};
    #pragma unroll 4
    for (int k = 0; k < HD; k++) {
        float4 a = *(const float4*)&A[k][tok0];
        float4 b = *(const float4*)&Ws[k][col0];
        acc[0][0] += a.x*b.x; acc[0][1] += a.x*b.y; acc[0][2] += a.x*b.z; acc[0][3] += a.x*b.w;
        acc[1][0] += a.y*b.x; acc[1][1] += a.y*b.y; acc[1][2] += a.y*b.z; acc[1][3] += a.y*b.w;
        acc[2][0] += a.z*b.x; acc[2][1] += a.z*b.y; acc[2][2] += a.z*b.z; acc[2][3] += a.z*b.w;
        acc[3][0] += a.w*b.x; acc[3][1] += a.w*b.y; acc[3][2] += a.w*b.z; acc[3][3] += a.w*b.w;
    }
    float b0 = bout[col0], b1 = bout[col0+1], b2 = bout[col0+2], b3 = bout[col0+3];
    #pragma unroll
    for (int ti = 0; ti < 4; ti++) {
        float4 v;
        v.x = acc[ti][0] + b0; v.y = acc[ti][1] + b1;
        v.z = acc[ti][2] + b2; v.w = acc[ti][3] + b3;
        *(float4*)&out[(base + tok0 + ti) * OD + col0] = v;
    }
}

// ---------------- launcher ----------------
extern "C" void kernel_launch(void* const* d_in, const int* in_sizes, int n_in,
                              void* d_out, int out_size)
{
    const float* x    = (const float*)d_in[0];
    const void*  isin = d_in[1];
    const float* hx   = (const float*)d_in[2];
    const float* W1   = (const float*)d_in[3];
    const float* b1   = (const float*)d_in[4];
    const float* g1   = (const float*)d_in[5];
    const float* be1  = (const float*)d_in[6];
    const float* W2   = (const float*)d_in[7];
    const float* b2   = (const float*)d_in[8];
    const float* g2   = (const float*)d_in[9];
    const float* be2  = (const float*)d_in[10];
    const float* Wih  = (const float*)d_in[11];
    const float* Whh  = (const float*)d_in[12];
    const float* bih  = (const float*)d_in[13];
    const float* bhh  = (const float*)d_in[14];
    const float* Wout = (const float*)d_in[15];
    const float* bout = (const float*)d_in[16];
    float* out = (float*)d_out;

    const int SM_FF  = SM_TOT;
    const int SM_REC = RSM_TOT;
    const int SM_OUT = 2 * 128 * 68 * (int)sizeof(float);
    cudaFuncSetAttribute(ff_kernel,  cudaFuncAttributeMaxDynamicSharedMemorySize, SM_FF);
    cudaFuncSetAttribute(rec_kernel, cudaFuncAttributeMaxDynamicSharedMemorySize, SM_REC);
    cudaFuncSetAttribute(out_kernel, cudaFuncAttributeMaxDynamicSharedMemorySize, SM_OUT);

    detect_kernel<<<1, 32>>>((const unsigned int*)isin);
    ff_kernel<<<BT_ / 128, 256, SM_FF>>>(x, W1, b1, g1, be1, W2, b2, g2, be2, Wih, bih);
    rec_kernel<<<B_ / 16, 256, SM_REC>>>(hx, Whh, bhh, isin, out + (size_t)BT_ * OD);
    out_kernel<<<BT_ / 64, 256, SM_OUT>>>(Wout, bout, out);
}

// round 8
// speedup vs baseline: 3.2702x; 1.0036x over previous
#include <cuda_runtime.h>
#include <cuda_bf16.h>
#include <math.h>
#include <stdint.h>

#define B_    1024
#define T_    512
#define BT_   (B_*T_)
#define IND   64
#define HD    128
#define G3    384
#define OD    64
#define NEG   0.01f
#define LNEPS 1e-5f

#define ASTR  136              // bf16 elements per smem row in ff (272 B)
#define SSTR  132              // fp32 stage stride in ff

// ---------------- scratch ----------------
static __device__ float g_gates[(size_t)BT_ * G3];   // [B*T, 384]
static __device__ float g_y[(size_t)BT_ * HD];       // [B*T, 128]
static __device__ int   g_wordmode;

__global__ void detect_kernel(const unsigned int* __restrict__ p) {
    if (threadIdx.x == 0) {
        int wm = 1;
        for (int i = 0; i < 256; i++) {
            unsigned v = p[i];
            if (v != 0u && v != 1u && v != 0x3F800000u) { wm = 0; break; }
        }
        g_wordmode = wm;
    }
}

// ---------------- mma.sync helpers ----------------
__device__ __forceinline__ uint32_t smem_u32(const void* p) {
    uint32_t a;
    asm("{ .reg .u64 t; cvta.to.shared.u64 t, %1; cvt.u32.u64 %0, t; }" : "=r"(a) : "l"(p));
    return a;
}
__device__ __forceinline__ void ldsm_x4(uint32_t* r, uint32_t addr) {
    asm volatile("ldmatrix.sync.aligned.m8n8.x4.shared.b16 {%0,%1,%2,%3}, [%4];"
                 : "=r"(r[0]), "=r"(r[1]), "=r"(r[2]), "=r"(r[3]) : "r"(addr));
}
__device__ __forceinline__ void mma16816(float* d, const uint32_t* a, const uint32_t* b) {
    asm volatile("mma.sync.aligned.m16n8k16.row.col.f32.bf16.bf16.f32 "
                 "{%0,%1,%2,%3}, {%4,%5,%6,%7}, {%8,%9}, {%0,%1,%2,%3};"
                 : "+f"(d[0]), "+f"(d[1]), "+f"(d[2]), "+f"(d[3])
                 : "r"(a[0]), "r"(a[1]), "r"(a[2]), "r"(a[3]), "r"(b[0]), "r"(b[1]));
}

// split fp32 pair -> bf16 hi/lo pairs
__device__ __forceinline__ void split2(__nv_bfloat16* hi, __nv_bfloat16* lo, int eo,
                                       float a, float b) {
    __nv_bfloat16 h0 = __float2bfloat16(a), h1 = __float2bfloat16(b);
    __nv_bfloat16 l0 = __float2bfloat16(a - __bfloat162float(h0));
    __nv_bfloat16 l1 = __float2bfloat16(b - __bfloat162float(h1));
    __nv_bfloat162 hh; hh.x = h0; hh.y = h1;
    __nv_bfloat162 ll; ll.x = l0; ll.y = l1;
    *(__nv_bfloat162*)(hi + eo) = hh;
    *(__nv_bfloat162*)(lo + eo) = ll;
}

// ============================== FF (unchanged, R6/R7) ==============================
template<int K>
__device__ __forceinline__ void conv_w(const float* __restrict__ W,
                                       __nv_bfloat16* bh, __nv_bfloat16* bl, int tid) {
    const int total = 128 * (K / 2);
    for (int p = tid; p < total; p += 256) {
        int row = p / (K / 2), kp = p % (K / 2);
        float2 v = *(const float2*)&W[row * K + 2 * kp];
        split2(bh, bl, row * ASTR + 2 * kp, v.x, v.y);
    }
}

template<int NK>
__device__ __forceinline__ void wgemm(uint32_t a_hi, uint32_t a_lo,
                                      uint32_t b_hi, uint32_t b_lo,
                                      float (*acc)[4], int warp, int lane)
{
    const int arow = 16 * warp + (lane & 7) + ((lane & 8) ? 8 : 0);
    const int acg  = (lane & 16) ? 8 : 0;
    const uint32_t aoff = (uint32_t)(arow * ASTR + acg) * 2;
    const int nloc = (lane & 7) + ((lane & 16) ? 8 : 0);
    const int bkg  = (lane & 8) ? 8 : 0;
    const uint32_t boff = (uint32_t)(nloc * ASTR + bkg) * 2;
    #pragma unroll
    for (int k0 = 0; k0 < NK; k0++) {
        uint32_t ah[4], al[4];
        ldsm_x4(ah, a_hi + aoff + k0 * 32);
        ldsm_x4(al, a_lo + aoff + k0 * 32);
        #pragma unroll
        for (int jp = 0; jp < 8; jp++) {
            uint32_t bo = boff + (uint32_t)(jp * 16 * ASTR) * 2 + k0 * 32;
            uint32_t bh[4], bl[4];
            ldsm_x4(bh, b_hi + bo);
            ldsm_x4(bl, b_lo + bo);
            mma16816(acc[2*jp],     ah, bh);
            mma16816(acc[2*jp],     ah, bl);
            mma16816(acc[2*jp],     al, bh);
            mma16816(acc[2*jp + 1], ah, bh + 2);
            mma16816(acc[2*jp + 1], ah, bl + 2);
            mma16816(acc[2*jp + 1], al, bh + 2);
        }
    }
}

__device__ __forceinline__ void ln_epi(float (*acc)[4],
    const float* __restrict__ bias, const float* __restrict__ gam, const float* __restrict__ bet,
    __nv_bfloat16* Ah, __nv_bfloat16* Al, int warp, int lane)
{
    const int r0 = 16 * warp + (lane >> 2), r1 = r0 + 8;
    float s0 = 0.f, q0 = 0.f, s1 = 0.f, q1 = 0.f;
    #pragma unroll
    for (int j = 0; j < 16; j++) {
        int col = 8 * j + 2 * (lane & 3);
        float bv0 = __ldg(&bias[col]), bv1 = __ldg(&bias[col + 1]);
        float v00 = acc[j][0] + bv0; v00 = v00 > 0.f ? v00 : NEG * v00;
        float v01 = acc[j][1] + bv1; v01 = v01 > 0.f ? v01 : NEG * v01;
        float v10 = acc[j][2] + bv0; v10 = v10 > 0.f ? v10 : NEG * v10;
        float v11 = acc[j][3] + bv1; v11 = v11 > 0.f ? v11 : NEG * v11;
        acc[j][0] = v00; acc[j][1] = v01; acc[j][2] = v10; acc[j][3] = v11;
        s0 += v00 + v01; q0 += v00 * v00 + v01 * v01;
        s1 += v10 + v11; q1 += v10 * v10 + v11 * v11;
    }
    s0 += __shfl_xor_sync(0xffffffffu, s0, 1); s0 += __shfl_xor_sync(0xffffffffu, s0, 2);
    q0 += __shfl_xor_sync(0xffffffffu, q0, 1); q0 += __shfl_xor_sync(0xffffffffu, q0, 2);
    s1 += __shfl_xor_sync(0xffffffffu, s1, 1); s1 += __shfl_xor_sync(0xffffffffu, s1, 2);
    q1 += __shfl_xor_sync(0xffffffffu, q1, 1); q1 += __shfl_xor_sync(0xffffffffu, q1, 2);
    float mu0 = s0 * (1.f / 128.f), rs0 = rsqrtf(q0 * (1.f / 128.f) - mu0 * mu0 + LNEPS);
    float mu1 = s1 * (1.f / 128.f), rs1 = rsqrtf(q1 * (1.f / 128.f) - mu1 * mu1 + LNEPS);
    #pragma unroll
    for (int j = 0; j < 16; j++) {
        int col = 8 * j + 2 * (lane & 3);
        float g0 = __ldg(&gam[col]), g1 = __ldg(&gam[col + 1]);
        float t0 = __ldg(&bet[col]), t1 = __ldg(&bet[col + 1]);
        split2(Ah, Al, r0 * ASTR + col,
               (acc[j][0] - mu0) * rs0 * g0 + t0, (acc[j][1] - mu0) * rs0 * g1 + t1);
        split2(Ah, Al, r1 * ASTR + col,
               (acc[j][2] - mu1) * rs1 * g0 + t0, (acc[j][3] - mu1) * rs1 * g1 + t1);
    }
}

__device__ __forceinline__ void gates_epi(float (*acc)[4], const float* __restrict__ bias,
                                          float* stage, int warp, int lane)
{
    const int r0 = 16 * warp + (lane >> 2), r1 = r0 + 8;
    #pragma unroll
    for (int j = 0; j < 16; j++) {
        int col = 8 * j + 2 * (lane & 3);
        float bv0 = __ldg(&bias[col]), bv1 = __ldg(&bias[col + 1]);
        *(float2*)&stage[r0 * SSTR + col] = make_float2(acc[j][0] + bv0, acc[j][1] + bv1);
        *(float2*)&stage[r1 * SSTR + col] = make_float2(acc[j][2] + bv0, acc[j][3] + bv1);
    }
}

#define SM_AH   0
#define SM_AL   (128 * ASTR * 2)
#define SM_BH   (2 * 128 * ASTR * 2)
#define SM_BL   (3 * 128 * ASTR * 2)
#define SM_STG  (4 * 128 * ASTR * 2)
#define SM_TOT  (SM_STG + 128 * SSTR * 4)

__global__ void __launch_bounds__(256) ff_kernel(
    const float* __restrict__ x,
    const float* __restrict__ W1, const float* __restrict__ b1,
    const float* __restrict__ g1, const float* __restrict__ be1,
    const float* __restrict__ W2, const float* __restrict__ b2,
    const float* __restrict__ g2, const float* __restrict__ be2,
    const float* __restrict__ Wih, const float* __restrict__ bih)
{
    extern __shared__ char smem[];
    __nv_bfloat16* Ah = (__nv_bfloat16*)(smem + SM_AH);
    __nv_bfloat16* Al = (__nv_bfloat16*)(smem + SM_AL);
    __nv_bfloat16* Bh = (__nv_bfloat16*)(smem + SM_BH);
    __nv_bfloat16* Bl = (__nv_bfloat16*)(smem + SM_BL);
    float* stage = (float*)(smem + SM_STG);
    const uint32_t a_hi = smem_u32(Ah), a_lo = smem_u32(Al);
    const uint32_t b_hi = smem_u32(Bh), b_lo = smem_u32(Bl);
    const int tid = threadIdx.x, warp = tid >> 5, lane = tid & 31;
    const size_t base = (size_t)blockIdx.x * 128;

    for (int p = tid; p < 128 * 32; p += 256) {
        int row = p >> 5, kp = p & 31;
        float2 v = *(const float2*)&x[(base + row) * IND + 2 * kp];
        split2(Ah, Al, row * ASTR + 2 * kp, v.x, v.y);
    }
    conv_w<IND>(W1, Bh, Bl, tid);
    __syncthreads();

    float acc[16][4];
    #pragma unroll
    for (int j = 0; j < 16; j++) { acc[j][0]=acc[j][1]=acc[j][2]=acc[j][3]=0.f; }
    wgemm<4>(a_hi, a_lo, b_hi, b_lo, acc, warp, lane);
    __syncthreads();
    ln_epi(acc, b1, g1, be1, Ah, Al, warp, lane);

    conv_w<HD>(W2, Bh, Bl, tid);
    __syncthreads();
    #pragma unroll
    for (int j = 0; j < 16; j++) { acc[j][0]=acc[j][1]=acc[j][2]=acc[j][3]=0.f; }
    wgemm<8>(a_hi, a_lo, b_hi, b_lo, acc, warp, lane);
    __syncthreads();
    ln_epi(acc, b2, g2, be2, Ah, Al, warp, lane);

    for (int c3 = 0; c3 < 3; c3++) {
        conv_w<HD>(Wih + (size_t)c3 * 128 * HD, Bh, Bl, tid);
        __syncthreads();
        #pragma unroll
        for (int j = 0; j < 16; j++) { acc[j][0]=acc[j][1]=acc[j][2]=acc[j][3]=0.f; }
        wgemm<8>(a_hi, a_lo, b_hi, b_lo, acc, warp, lane);
        gates_epi(acc, bih + c3 * 128, stage, warp, lane);
        __syncthreads();
        float* gout = g_gates + base * G3 + c3 * 128;
        for (int it = tid; it < 128 * 128; it += 256) {
            int r = it >> 7, cc = it & 127;
            gout[(size_t)r * G3 + cc] = stage[r * SSTR + cc];
        }
        __syncthreads();
    }
}

// ============================== REC v2: in-register epilogue ==============================
// smem: W hi/lo [384][128] bf16 swizzled 256B rows; A double-buffered hi/lo (16x128 each)
#define RSM_WH  0
#define RSM_WL  98304
#define RSM_A   196608                 // buf b: hi at +b*8192, lo at +b*8192+4096
#define RSM_TOT (RSM_A + 16384)        // 212992

__device__ __forceinline__ float sigf(float x) {
    float e = __expf(-x);
    return __fdividef(1.f, 1.f + e);
}
__device__ __forceinline__ float tanhf_fast(float x) {
    return fmaf(2.f, sigf(2.f * x), -1.f);
}

// store split float2 of batch b at even column j into A buffer (swizzled 256B rows)
__device__ __forceinline__ void stA2(char* AH, char* AL, int b, int j, float2 h) {
    uint32_t off = (uint32_t)(b * 256 + (((j >> 3) ^ (b & 7)) << 4) + (j & 7) * 2);
    split2((__nv_bfloat16*)(AH + off), (__nv_bfloat16*)(AL + off), 0, h.x, h.y);
}

__global__ void __launch_bounds__(256, 1) rec_kernel(
    const float* __restrict__ hx, const float* __restrict__ Whh,
    const float* __restrict__ bhh, const void* __restrict__ isinit,
    float* __restrict__ hxout)
{
    extern __shared__ char sm[];
    char* WH = sm + RSM_WH;
    char* WL = sm + RSM_WL;
    const uint32_t whb = smem_u32(WH), wlb = smem_u32(WL);
    const uint32_t aab = smem_u32(sm + RSM_A);
    const int tid = threadIdx.x, warp = tid >> 5, lane = tid & 31;
    const int b0 = blockIdx.x * 16;

    // ---- prologue: W_hh -> bf16 hi/lo, swizzled [col][k] 256B rows ----
    for (int p = tid; p < 384 * 64; p += 256) {
        int row = p >> 6, kp = p & 63, k = kp * 2;
        float2 v = *(const float2*)&Whh[row * 128 + k];
        uint32_t off = (uint32_t)(row * 256 + (((k >> 3) ^ (row & 7)) << 4) + (k & 7) * 2);
        split2((__nv_bfloat16*)(WH + off), (__nv_bfloat16*)(WL + off), 0, v.x, v.y);
    }

    // thread-owned coordinates:
    //   batches: bA = lane>>2 and bA+8
    //   columns: j = 16*warp + 8*p + c0 + {0,1}, p in {0,1}, c0 = 2*(lane&3)
    const int bA = lane >> 2;
    const int c0 = 2 * (lane & 3);
    const int jb = 16 * warp + c0;

    // bias fragments bv[gate][p][q]
    float bv[3][2][2];
    #pragma unroll
    for (int g = 0; g < 3; g++)
        #pragma unroll
        for (int p = 0; p < 2; p++) {
            int col = g * 128 + jb + 8 * p;
            bv[g][p][0] = __ldg(&bhh[col]);
            bv[g][p][1] = __ldg(&bhh[col + 1]);
        }

    const int wm = g_wordmode;
    const unsigned int*  ii32 = (const unsigned int*)isinit;
    const unsigned char* ii8  = (const unsigned char*)isinit;

    // h_prev registers + initial A build (t=0) into buffer 0
    float hprev[2][2][2];
    float gxc[2][3][2][2];
    {
        char* AH0 = sm + RSM_A;
        char* AL0 = AH0 + 4096;
        #pragma unroll
        for (int bi = 0; bi < 2; bi++) {
            int b = bA + 8 * bi;
            size_t ib = (size_t)(b0 + b) * T_;
            int f0 = wm ? (ii32[ib] != 0u) : (ii8[ib] != 0);
            #pragma unroll
            for (int p = 0; p < 2; p++) {
                float2 v = *(const float2*)&hx[(size_t)(b0 + b) * HD + jb + 8 * p];
                if (f0) { v.x = 0.f; v.y = 0.f; }
                hprev[bi][p][0] = v.x; hprev[bi][p][1] = v.y;
                stA2(AH0, AL0, b, jb + 8 * p, v);
            }
            #pragma unroll
            for (int g = 0; g < 3; g++)
                #pragma unroll
                for (int p = 0; p < 2; p++) {
                    float2 v = *(const float2*)&g_gates[ib * G3 + g * 128 + jb + 8 * p];
                    gxc[bi][g][p][0] = v.x; gxc[bi][g][p][1] = v.y;
                }
        }
    }

    // ldmatrix addressing (constant)
    const int arow = lane & 15;
    const uint32_t abase = (uint32_t)(arow * 256);
    const int achx = (lane & 16) ? 1 : 0, arx = arow & 7;
    const int nloc = (lane & 7) + ((lane & 16) ? 8 : 0);
    const int bchx = (lane & 8) ? 1 : 0;

    __syncthreads();   // W + A0 ready

    int cur = 0;
    for (int t = 0; t < T_; t++) {
        // prefetch next-step gx + flags (overlaps MMA below)
        float ngx[2][3][2][2];
        int nf[2]; nf[0] = 0; nf[1] = 0;
        if (t + 1 < T_) {
            #pragma unroll
            for (int bi = 0; bi < 2; bi++) {
                size_t ib = (size_t)(b0 + bA + 8 * bi) * T_ + (t + 1);
                nf[bi] = wm ? (ii32[ib] != 0u) : (ii8[ib] != 0);
                #pragma unroll
                for (int g = 0; g < 3; g++)
                    #pragma unroll
                    for (int p = 0; p < 2; p++) {
                        float2 v = *(const float2*)&g_gates[ib * G3 + g * 128 + jb + 8 * p];
                        ngx[bi][g][p][0] = v.x; ngx[bi][g][p][1] = v.y;
                    }
            }
        }

        // ---- MMA: warp w computes gates r,z,n for j in [16w,16w+16), 16 batches ----
        float acc[3][2][4];
        #pragma unroll
        for (int g = 0; g < 3; g++)
            #pragma unroll
            for (int p = 0; p < 2; p++) {
                acc[g][p][0] = bv[g][p][0]; acc[g][p][1] = bv[g][p][1];
                acc[g][p][2] = bv[g][p][0]; acc[g][p][3] = bv[g][p][1];
            }
        const uint32_t ahb = aab + (uint32_t)cur * 8192;
        const uint32_t alb = ahb + 4096;
        #pragma unroll
        for (int k0 = 0; k0 < 8; k0++) {
            uint32_t ach = (uint32_t)((2 * k0 + achx) ^ arx);
            uint32_t ah4[4], al4[4];
            ldsm_x4(ah4, ahb + abase + (ach << 4));
            ldsm_x4(al4, alb + abase + (ach << 4));
            #pragma unroll
            for (int g = 0; g < 3; g++) {
                int n = g * 128 + 16 * warp + nloc;
                uint32_t bch = (uint32_t)((2 * k0 + bchx) ^ (n & 7));
                uint32_t boff = (uint32_t)(n * 256) + (bch << 4);
                uint32_t bh4[4], bl4[4];
                ldsm_x4(bh4, whb + boff);
                ldsm_x4(bl4, wlb + boff);
                mma16816(acc[g][0], ah4, bh4);
                mma16816(acc[g][0], ah4, bl4);
                mma16816(acc[g][0], al4, bh4);
                mma16816(acc[g][1], ah4, bh4 + 2);
                mma16816(acc[g][1], ah4, bl4 + 2);
                mma16816(acc[g][1], al4, bh4 + 2);
            }
        }

        // ---- in-register GRU epilogue ----
        const int nxt = cur ^ 1;
        char* AHn = sm + RSM_A + nxt * 8192;
        char* ALn = AHn + 4096;
        #pragma unroll
        for (int bi = 0; bi < 2; bi++) {
            int b = bA + 8 * bi;
            float hnew[2][2];
            #pragma unroll
            for (int p = 0; p < 2; p++) {
                #pragma unroll
                for (int q = 0; q < 2; q++) {
                    float r = sigf(gxc[bi][0][p][q] + acc[0][p][2 * bi + q]);
                    float z = sigf(gxc[bi][1][p][q] + acc[1][p][2 * bi + q]);
                    float n = tanhf_fast(gxc[bi][2][p][q] + r * acc[2][p][2 * bi + q]);
                    hnew[p][q] = (1.f - z) * n + z * hprev[bi][p][q];
                }
                *(float2*)&g_y[((size_t)(b0 + b) * T_ + t) * HD + jb + 8 * p] =
                    make_float2(hnew[p][0], hnew[p][1]);
            }
            if (t + 1 < T_) {
                #pragma unroll
                for (int p = 0; p < 2; p++) {
                    float2 he = nf[bi] ? make_float2(0.f, 0.f)
                                       : make_float2(hnew[p][0], hnew[p][1]);
                    hprev[bi][p][0] = he.x; hprev[bi][p][1] = he.y;
                    stA2(AHn, ALn, b, jb + 8 * p, he);
                }
            } else {
                #pragma unroll
                for (int p = 0; p < 2; p++)
                    *(float2*)&hxout[(size_t)(b0 + b) * HD + jb + 8 * p] =
                        make_float2(hnew[p][0], hnew[p][1]);
            }
        }
        if (t + 1 < T_) {
            #pragma unroll
            for (int bi = 0; bi < 2; bi++)
                #pragma unroll
                for (int g = 0; g < 3; g++)
                    #pragma unroll
                    for (int p = 0; p < 2; p++) {
                        gxc[bi][g][p][0] = ngx[bi][g][p][0];
                        gxc[bi][g][p][1] = ngx[bi][g][p][1];
                    }
        }
        cur = nxt;
        __syncthreads();   // A(nxt) complete before anyone reads it
    }
}

// ---------------- output projection: HMMA bf16-split ----------------
// A: y tile 128x128 split; B: Wout 64x128 split. 8 warps x (16 tokens x 64 cols).
#define OSM_AH  0
#define OSM_AL  (128 * ASTR * 2)
#define OSM_BH  (2 * 128 * ASTR * 2)
#define OSM_BL  (OSM_BH + 64 * ASTR * 2)
#define OSM_TOT (OSM_BH + 2 * 64 * ASTR * 2)

__global__ void __launch_bounds__(256, 2) out_kernel(
    const float* __restrict__ Wout, const float* __restrict__ bout,
    float* __restrict__ out)
{
    extern __shared__ char smem[];
    __nv_bfloat16* Ah = (__nv_bfloat16*)(smem + OSM_AH);
    __nv_bfloat16* Al = (__nv_bfloat16*)(smem + OSM_AL);
    __nv_bfloat16* Bh = (__nv_bfloat16*)(smem + OSM_BH);
    __nv_bfloat16* Bl = (__nv_bfloat16*)(smem + OSM_BL);
    const uint32_t a_hi = smem_u32(Ah), a_lo = smem_u32(Al);
    const uint32_t b_hi = smem_u32(Bh), b_lo = smem_u32(Bl);
    const int tid = threadIdx.x, warp = tid >> 5, lane = tid & 31;
    const size_t base = (size_t)blockIdx.x * 128;

    for (int p = tid; p < 128 * 64; p += 256) {
        int row = p >> 6, kp = p & 63;
        float2 v = *(const float2*)&g_y[(base + row) * HD + 2 * kp];
        split2(Ah, Al, row * ASTR + 2 * kp, v.x, v.y);
    }
    for (int p = tid; p < 64 * 64; p += 256) {
        int row = p >> 6, kp = p & 63;
        float2 v = *(const float2*)&Wout[row * HD + 2 * kp];
        split2(Bh, Bl, row * ASTR + 2 * kp, v.x, v.y);
    }
    __syncthreads();

    float acc[8][4];
    #pragma unroll
    for (int j = 0; j < 8; j++) { acc[j][0]=acc[j][1]=acc[j][2]=acc[j][3]=0.f; }

    const int arow = 16 * warp + (lane & 7) + ((lane & 8) ? 8 : 0);
    const int acg  = (lane & 16) ? 8 : 0;
    const uint32_t aoff = (uint32_t)(arow * ASTR + acg) * 2;
    const int nloc = (lane & 7) + ((lane & 16) ? 8 : 0);
    const int bkg  = (lane & 8) ? 8 : 0;
    const uint32_t boff = (uint32_t)(nloc * ASTR + bkg) * 2;
    #pragma unroll
    for (int k0 = 0; k0 < 8; k0++) {
        uint32_t ah[4], al[4];
        ldsm_x4(ah, a_hi + aoff + k0 * 32);
        ldsm_x4(al, a_lo + aoff + k0 * 32);
        #pragma unroll
        for (int jp = 0; jp < 4; jp++) {
            uint32_t bo = boff + (uint32_t)(jp * 16 * ASTR) * 2 + k0 * 32;
            uint32_t bh[4], bl[4];
            ldsm_x4(bh, b_hi + bo);
            ldsm_x4(bl, b_lo + bo);
            mma16816(acc[2*jp],     ah, bh);
            mma16816(acc[2*jp],     ah, bl);
            mma16816(acc[2*jp],     al, bh);
            mma16816(acc[2*jp + 1], ah, bh + 2);
            mma16816(acc[2*jp + 1], ah, bl + 2);
            mma16816(acc[2*jp + 1], al, bh + 2);
        }
    }

    const int r0 = 16 * warp + (lane >> 2), r1 = r0 + 8;
    #pragma unroll
    for (int j = 0; j < 8; j++) {
        int col = 8 * j + 2 * (lane & 3);
        float bv0 = __ldg(&bout[col]), bv1 = __ldg(&bout[col + 1]);
        *(float2*)&out[(base + r0) * OD + col] = make_float2(acc[j][0] + bv0, acc[j][1] + bv1);
        *(float2*)&out[(base + r1) * OD + col] = make_float2(acc[j][2] + bv0, acc[j][3] + bv1);
    }
}

// ---------------- launcher ----------------
extern "C" void kernel_launch(void* const* d_in, const int* in_sizes, int n_in,
                              void* d_out, int out_size)
{
    const float* x    = (const float*)d_in[0];
    const void*  isin = d_in[1];
    const float* hx   = (const float*)d_in[2];
    const float* W1   = (const float*)d_in[3];
    const float* b1   = (const float*)d_in[4];
    const float* g1   = (const float*)d_in[5];
    const float* be1  = (const float*)d_in[6];
    const float* W2   = (const float*)d_in[7];
    const float* b2   = (const float*)d_in[8];
    const float* g2   = (const float*)d_in[9];
    const float* be2  = (const float*)d_in[10];
    const float* Wih  = (const float*)d_in[11];
    const float* Whh  = (const float*)d_in[12];
    const float* bih  = (const float*)d_in[13];
    const float* bhh  = (const float*)d_in[14];
    const float* Wout = (const float*)d_in[15];
    const float* bout = (const float*)d_in[16];
    float* out = (float*)d_out;

    const int SM_FF  = SM_TOT;
    const int SM_REC = RSM_TOT;
    const int SM_OUT = OSM_TOT;
    cudaFuncSetAttribute(ff_kernel,  cudaFuncAttributeMaxDynamicSharedMemorySize, SM_FF);
    cudaFuncSetAttribute(rec_kernel, cudaFuncAttributeMaxDynamicSharedMemorySize, SM_REC);
    cudaFuncSetAttribute(out_kernel, cudaFuncAttributeMaxDynamicSharedMemorySize, SM_OUT);

    detect_kernel<<<1, 32>>>((const unsigned int*)isin);
    ff_kernel<<<BT_ / 128, 256, SM_FF>>>(x, W1, b1, g1, be1, W2, b2, g2, be2, Wih, bih);
    rec_kernel<<<B_ / 16, 256, SM_REC>>>(hx, Whh, bhh, isin, out + (size_t)BT_ * OD);
    out_kernel<<<BT_ / 128, 256, SM_OUT>>>(Wout, bout, out);
}

// round 9
// speedup vs baseline: 3.3161x; 1.0140x over previous
#include <cuda_runtime.h>
#include <cuda_bf16.h>
#include <math.h>
#include <stdint.h>

#define B_    1024
#define T_    512
#define BT_   (B_*T_)
#define IND   64
#define HD    128
#define G3    384
#define OD    64
#define NEG   0.01f
#define LNEPS 1e-5f

#define ASTR  136
#define SSTR  132

// ---------------- scratch ----------------
static __device__ float g_gates[(size_t)BT_ * G3];   // [B*T, 384]
static __device__ float g_y[(size_t)BT_ * HD];       // [B*T, 128]
static __device__ int   g_wordmode;

__global__ void detect_kernel(const unsigned int* __restrict__ p) {
    __shared__ int bad;
    if (threadIdx.x == 0) bad = 0;
    __syncthreads();
    unsigned v = p[threadIdx.x];
    if (v != 0u && v != 1u && v != 0x3F800000u) atomicExch(&bad, 1);
    __syncthreads();
    if (threadIdx.x == 0) g_wordmode = bad ? 0 : 1;
}

// ---------------- mma.sync helpers ----------------
__device__ __forceinline__ uint32_t smem_u32(const void* p) {
    uint32_t a;
    asm("{ .reg .u64 t; cvta.to.shared.u64 t, %1; cvt.u32.u64 %0, t; }" : "=r"(a) : "l"(p));
    return a;
}
__device__ __forceinline__ void ldsm_x4(uint32_t* r, uint32_t addr) {
    asm volatile("ldmatrix.sync.aligned.m8n8.x4.shared.b16 {%0,%1,%2,%3}, [%4];"
                 : "=r"(r[0]), "=r"(r[1]), "=r"(r[2]), "=r"(r[3]) : "r"(addr));
}
__device__ __forceinline__ void mma16816(float* d, const uint32_t* a, const uint32_t* b) {
    asm volatile("mma.sync.aligned.m16n8k16.row.col.f32.bf16.bf16.f32 "
                 "{%0,%1,%2,%3}, {%4,%5,%6,%7}, {%8,%9}, {%0,%1,%2,%3};"
                 : "+f"(d[0]), "+f"(d[1]), "+f"(d[2]), "+f"(d[3])
                 : "r"(a[0]), "r"(a[1]), "r"(a[2]), "r"(a[3]), "r"(b[0]), "r"(b[1]));
}

__device__ __forceinline__ void split2(__nv_bfloat16* hi, __nv_bfloat16* lo, int eo,
                                       float a, float b) {
    __nv_bfloat16 h0 = __float2bfloat16(a), h1 = __float2bfloat16(b);
    __nv_bfloat16 l0 = __float2bfloat16(a - __bfloat162float(h0));
    __nv_bfloat16 l1 = __float2bfloat16(b - __bfloat162float(h1));
    __nv_bfloat162 hh; hh.x = h0; hh.y = h1;
    __nv_bfloat162 ll; ll.x = l0; ll.y = l1;
    *(__nv_bfloat162*)(hi + eo) = hh;
    *(__nv_bfloat162*)(lo + eo) = ll;
}

// ============================== FF (unchanged, validated) ==============================
template<int K>
__device__ __forceinline__ void conv_w(const float* __restrict__ W,
                                       __nv_bfloat16* bh, __nv_bfloat16* bl, int tid) {
    const int total = 128 * (K / 2);
    for (int p = tid; p < total; p += 256) {
        int row = p / (K / 2), kp = p % (K / 2);
        float2 v = *(const float2*)&W[row * K + 2 * kp];
        split2(bh, bl, row * ASTR + 2 * kp, v.x, v.y);
    }
}

template<int NK>
__device__ __forceinline__ void wgemm(uint32_t a_hi, uint32_t a_lo,
                                      uint32_t b_hi, uint32_t b_lo,
                                      float (*acc)[4], int warp, int lane)
{
    const int arow = 16 * warp + (lane & 7) + ((lane & 8) ? 8 : 0);
    const int acg  = (lane & 16) ? 8 : 0;
    const uint32_t aoff = (uint32_t)(arow * ASTR + acg) * 2;
    const int nloc = (lane & 7) + ((lane & 16) ? 8 : 0);
    const int bkg  = (lane & 8) ? 8 : 0;
    const uint32_t boff = (uint32_t)(nloc * ASTR + bkg) * 2;
    #pragma unroll
    for (int k0 = 0; k0 < NK; k0++) {
        uint32_t ah[4], al[4];
        ldsm_x4(ah, a_hi + aoff + k0 * 32);
        ldsm_x4(al, a_lo + aoff + k0 * 32);
        #pragma unroll
        for (int jp = 0; jp < 8; jp++) {
            uint32_t bo = boff + (uint32_t)(jp * 16 * ASTR) * 2 + k0 * 32;
            uint32_t bh[4], bl[4];
            ldsm_x4(bh, b_hi + bo);
            ldsm_x4(bl, b_lo + bo);
            mma16816(acc[2*jp],     ah, bh);
            mma16816(acc[2*jp],     ah, bl);
            mma16816(acc[2*jp],     al, bh);
            mma16816(acc[2*jp + 1], ah, bh + 2);
            mma16816(acc[2*jp + 1], ah, bl + 2);
            mma16816(acc[2*jp + 1], al, bh + 2);
        }
    }
}

__device__ __forceinline__ void ln_epi(float (*acc)[4],
    const float* __restrict__ bias, const float* __restrict__ gam, const float* __restrict__ bet,
    __nv_bfloat16* Ah, __nv_bfloat16* Al, int warp, int lane)
{
    const int r0 = 16 * warp + (lane >> 2), r1 = r0 + 8;
    float s0 = 0.f, q0 = 0.f, s1 = 0.f, q1 = 0.f;
    #pragma unroll
    for (int j = 0; j < 16; j++) {
        int col = 8 * j + 2 * (lane & 3);
        float bv0 = __ldg(&bias[col]), bv1 = __ldg(&bias[col + 1]);
        float v00 = acc[j][0] + bv0; v00 = v00 > 0.f ? v00 : NEG * v00;
        float v01 = acc[j][1] + bv1; v01 = v01 > 0.f ? v01 : NEG * v01;
        float v10 = acc[j][2] + bv0; v10 = v10 > 0.f ? v10 : NEG * v10;
        float v11 = acc[j][3] + bv1; v11 = v11 > 0.f ? v11 : NEG * v11;
        acc[j][0] = v00; acc[j][1] = v01; acc[j][2] = v10; acc[j][3] = v11;
        s0 += v00 + v01; q0 += v00 * v00 + v01 * v01;
        s1 += v10 + v11; q1 += v10 * v10 + v11 * v11;
    }
    s0 += __shfl_xor_sync(0xffffffffu, s0, 1); s0 += __shfl_xor_sync(0xffffffffu, s0, 2);
    q0 += __shfl_xor_sync(0xffffffffu, q0, 1); q0 += __shfl_xor_sync(0xffffffffu, q0, 2);
    s1 += __shfl_xor_sync(0xffffffffu, s1, 1); s1 += __shfl_xor_sync(0xffffffffu, s1, 2);
    q1 += __shfl_xor_sync(0xffffffffu, q1, 1); q1 += __shfl_xor_sync(0xffffffffu, q1, 2);
    float mu0 = s0 * (1.f / 128.f), rs0 = rsqrtf(q0 * (1.f / 128.f) - mu0 * mu0 + LNEPS);
    float mu1 = s1 * (1.f / 128.f), rs1 = rsqrtf(q1 * (1.f / 128.f) - mu1 * mu1 + LNEPS);
    #pragma unroll
    for (int j = 0; j < 16; j++) {
        int col = 8 * j + 2 * (lane & 3);
        float g0 = __ldg(&gam[col]), g1 = __ldg(&gam[col + 1]);
        float t0 = __ldg(&bet[col]), t1 = __ldg(&bet[col + 1]);
        split2(Ah, Al, r0 * ASTR + col,
               (acc[j][0] - mu0) * rs0 * g0 + t0, (acc[j][1] - mu0) * rs0 * g1 + t1);
        split2(Ah, Al, r1 * ASTR + col,
               (acc[j][2] - mu1) * rs1 * g0 + t0, (acc[j][3] - mu1) * rs1 * g1 + t1);
    }
}

__device__ __forceinline__ void gates_epi(float (*acc)[4], const float* __restrict__ bias,
                                          float* stage, int warp, int lane)
{
    const int r0 = 16 * warp + (lane >> 2), r1 = r0 + 8;
    #pragma unroll
    for (int j = 0; j < 16; j++) {
        int col = 8 * j + 2 * (lane & 3);
        float bv0 = __ldg(&bias[col]), bv1 = __ldg(&bias[col + 1]);
        *(float2*)&stage[r0 * SSTR + col] = make_float2(acc[j][0] + bv0, acc[j][1] + bv1);
        *(float2*)&stage[r1 * SSTR + col] = make_float2(acc[j][2] + bv0, acc[j][3] + bv1);
    }
}

#define SM_AH   0
#define SM_AL   (128 * ASTR * 2)
#define SM_BH   (2 * 128 * ASTR * 2)
#define SM_BL   (3 * 128 * ASTR * 2)
#define SM_STG  (4 * 128 * ASTR * 2)
#define SM_TOT  (SM_STG + 128 * SSTR * 4)

__global__ void __launch_bounds__(256) ff_kernel(
    const float* __restrict__ x,
    const float* __restrict__ W1, const float* __restrict__ b1,
    const float* __restrict__ g1, const float* __restrict__ be1,
    const float* __restrict__ W2, const float* __restrict__ b2,
    const float* __restrict__ g2, const float* __restrict__ be2,
    const float* __restrict__ Wih, const float* __restrict__ bih)
{
    extern __shared__ char smem[];
    __nv_bfloat16* Ah = (__nv_bfloat16*)(smem + SM_AH);
    __nv_bfloat16* Al = (__nv_bfloat16*)(smem + SM_AL);
    __nv_bfloat16* Bh = (__nv_bfloat16*)(smem + SM_BH);
    __nv_bfloat16* Bl = (__nv_bfloat16*)(smem + SM_BL);
    float* stage = (float*)(smem + SM_STG);
    const uint32_t a_hi = smem_u32(Ah), a_lo = smem_u32(Al);
    const uint32_t b_hi = smem_u32(Bh), b_lo = smem_u32(Bl);
    const int tid = threadIdx.x, warp = tid >> 5, lane = tid & 31;
    const size_t base = (size_t)blockIdx.x * 128;

    for (int p = tid; p < 128 * 32; p += 256) {
        int row = p >> 5, kp = p & 31;
        float2 v = *(const float2*)&x[(base + row) * IND + 2 * kp];
        split2(Ah, Al, row * ASTR + 2 * kp, v.x, v.y);
    }
    conv_w<IND>(W1, Bh, Bl, tid);
    __syncthreads();

    float acc[16][4];
    #pragma unroll
    for (int j = 0; j < 16; j++) { acc[j][0]=acc[j][1]=acc[j][2]=acc[j][3]=0.f; }
    wgemm<4>(a_hi, a_lo, b_hi, b_lo, acc, warp, lane);
    __syncthreads();
    ln_epi(acc, b1, g1, be1, Ah, Al, warp, lane);

    conv_w<HD>(W2, Bh, Bl, tid);
    __syncthreads();
    #pragma unroll
    for (int j = 0; j < 16; j++) { acc[j][0]=acc[j][1]=acc[j][2]=acc[j][3]=0.f; }
    wgemm<8>(a_hi, a_lo, b_hi, b_lo, acc, warp, lane);
    __syncthreads();
    ln_epi(acc, b2, g2, be2, Ah, Al, warp, lane);

    for (int c3 = 0; c3 < 3; c3++) {
        conv_w<HD>(Wih + (size_t)c3 * 128 * HD, Bh, Bl, tid);
        __syncthreads();
        #pragma unroll
        for (int j = 0; j < 16; j++) { acc[j][0]=acc[j][1]=acc[j][2]=acc[j][3]=0.f; }
        wgemm<8>(a_hi, a_lo, b_hi, b_lo, acc, warp, lane);
        gates_epi(acc, bih + c3 * 128, stage, warp, lane);
        __syncthreads();
        float* gout = g_gates + base * G3 + c3 * 128;
        for (int it = tid; it < 128 * 128; it += 256) {
            int r = it >> 7, cc = it & 127;
            gout[(size_t)r * G3 + cc] = stage[r * SSTR + cc];
        }
        __syncthreads();
    }
}

// ============================== REC v3: cluster-2 j-split ==============================
// Each cluster = 2 CTAs sharing 16 batches; rank r owns gate columns [64r, 64r+64).
// smem: W hi/lo [192 rows][128 k] swizzled 256B rows; A double-buffered (16x128 hi/lo);
// one mbarrier (512 arrivals = 256 local + 256 remote).
#define RSM_WH  0
#define RSM_WL  49152
#define RSM_A   98304
#define RSM_MB  (RSM_A + 16384)
#define RSM_TOT (RSM_MB + 16)     // 114704

__device__ __forceinline__ float sigf(float x) {
    float e = __expf(-x);
    return __fdividef(1.f, 1.f + e);
}
__device__ __forceinline__ float tanhf_fast(float x) {
    return fmaf(2.f, sigf(2.f * x), -1.f);
}

#define MBAR_INIT(m, n)  asm volatile("mbarrier.init.shared.b64 [%0], %1;" :: "r"(m), "r"(n) : "memory")
#define MBAR_ARRIVE_LOCAL(m) \
    asm volatile("mbarrier.arrive.release.cluster.shared::cta.b64 _, [%0];" :: "r"(m) : "memory")
#define MBAR_ARRIVE_REMOTE(m) \
    asm volatile("mbarrier.arrive.release.cluster.shared::cluster.b64 _, [%0];" :: "r"(m) : "memory")
#define MBAR_WAIT_CL(mb, ph) do {                                              \
    uint32_t _m = (mb); uint32_t _p = (ph); uint32_t _d;                       \
    asm volatile("{\n\t.reg .pred p;\n\t"                                      \
        "mbarrier.try_wait.parity.acquire.cluster.shared::cta.b64 p, [%1], %2;\n\t" \
        "selp.b32 %0, 1, 0, p;\n\t}"                                           \
        : "=r"(_d) : "r"(_m), "r"(_p) : "memory");                             \
    if (!_d) {                                                                 \
        asm volatile("{\n\t.reg .pred P1;\n\t"                                 \
            "W_%=:\n\t"                                                        \
            "mbarrier.try_wait.parity.acquire.cluster.shared::cta.b64 P1, [%0], %1, 0x989680;\n\t" \
            "@P1 bra.uni D_%=;\n\tbra.uni W_%=;\n\tD_%=:\n\t}"                 \
            :: "r"(_m), "r"(_p) : "memory");                                   \
    }                                                                          \
} while (0)

// split float2 -> hi/lo words, store to local buffer and peer buffer (j even)
__device__ __forceinline__ void stA2_both(char* AHl, uint32_t AHp, int b, int j, float2 h) {
    uint32_t off = (uint32_t)(b * 256 + (((j >> 3) ^ (b & 7)) << 4) + (j & 7) * 2);
    __nv_bfloat16 h0 = __float2bfloat16(h.x), h1 = __float2bfloat16(h.y);
    __nv_bfloat16 l0 = __float2bfloat16(h.x - __bfloat162float(h0));
    __nv_bfloat16 l1 = __float2bfloat16(h.y - __bfloat162float(h1));
    __nv_bfloat162 hh; hh.x = h0; hh.y = h1;
    __nv_bfloat162 ll; ll.x = l0; ll.y = l1;
    uint32_t hw = *(uint32_t*)&hh, lw = *(uint32_t*)&ll;
    *(uint32_t*)(AHl + off) = hw;
    *(uint32_t*)(AHl + 4096 + off) = lw;
    asm volatile("st.shared::cluster.u32 [%0], %1;" :: "r"(AHp + off), "r"(hw) : "memory");
    asm volatile("st.shared::cluster.u32 [%0], %1;" :: "r"(AHp + 4096 + off), "r"(lw) : "memory");
}

__global__ void __launch_bounds__(256, 1) __cluster_dims__(2, 1, 1)
rec_kernel(
    const float* __restrict__ hx, const float* __restrict__ Whh,
    const float* __restrict__ bhh, const void* __restrict__ isinit,
    float* __restrict__ hxout)
{
    extern __shared__ char sm[];
    char* WH = sm + RSM_WH;
    char* WL = sm + RSM_WL;
    const uint32_t whb = smem_u32(WH), wlb = smem_u32(WL);
    const uint32_t aab = smem_u32(sm + RSM_A);
    const uint32_t mbar = smem_u32(sm + RSM_MB);
    const int tid = threadIdx.x, warp = tid >> 5, lane = tid & 31;

    uint32_t rank;
    asm("mov.u32 %0, %%cluster_ctarank;" : "=r"(rank));
    const uint32_t peer = rank ^ 1u;
    const int b0 = (blockIdx.x >> 1) * 16;
    const int jhalf = (int)rank * 64;

    uint32_t aab_peer, mbar_peer;
    asm("mapa.shared::cluster.u32 %0, %1, %2;" : "=r"(aab_peer)  : "r"(aab),  "r"(peer));
    asm("mapa.shared::cluster.u32 %0, %1, %2;" : "=r"(mbar_peer) : "r"(mbar), "r"(peer));

    if (tid == 0) MBAR_INIT(mbar, 512);

    // ---- W_hh conversion: only this rank's 192 gate-column rows ----
    for (int p = tid; p < 192 * 64; p += 256) {
        int row_local = p >> 6, kp = p & 63, k = 2 * kp;
        int g = row_local >> 6, jn = row_local & 63;
        int grow = (g << 7) + jhalf + jn;
        float2 v = *(const float2*)&Whh[grow * 128 + k];
        uint32_t off = (uint32_t)(row_local * 256 + (((k >> 3) ^ (row_local & 7)) << 4) + (k & 7) * 2);
        split2((__nv_bfloat16*)(WH + off), (__nv_bfloat16*)(WL + off), 0, v.x, v.y);
    }

    // thread coordinates: batches bA, bA+8; columns j_g, j_g+1 (global)
    const int bA = lane >> 2;
    const int j_g = jhalf + 8 * warp + 2 * (lane & 3);

    float bv[3][2];
    #pragma unroll
    for (int g = 0; g < 3; g++) {
        int col = g * 128 + j_g;
        bv[g][0] = __ldg(&bhh[col]);
        bv[g][1] = __ldg(&bhh[col + 1]);
    }

    const int wm = g_wordmode;
    const unsigned int*  ii32 = (const unsigned int*)isinit;
    const unsigned char* ii8  = (const unsigned char*)isinit;

    // ---- A0 build (own j-half, local + peer) + gx(t=0) prefetch ----
    float hprev[2][2];
    float gxc[2][3][2];
    {
        char* AH0 = sm + RSM_A;
        uint32_t pAH0 = aab_peer;
        #pragma unroll
        for (int bi = 0; bi < 2; bi++) {
            int b = bA + 8 * bi;
            size_t ib = (size_t)(b0 + b) * T_;
            int f0 = wm ? (ii32[ib] != 0u) : (ii8[ib] != 0);
            float2 v = *(const float2*)&hx[(size_t)(b0 + b) * HD + j_g];
            if (f0) { v.x = 0.f; v.y = 0.f; }
            hprev[bi][0] = v.x; hprev[bi][1] = v.y;
            stA2_both(AH0, pAH0, b, j_g, v);
            #pragma unroll
            for (int g = 0; g < 3; g++) {
                float2 gv = *(const float2*)&g_gates[ib * G3 + g * 128 + j_g];
                gxc[bi][g][0] = gv.x; gxc[bi][g][1] = gv.y;
            }
        }
    }

    // cluster barrier: W, A0 (incl. remote halves), mbarrier init all visible
    asm volatile("barrier.cluster.arrive.aligned;" ::: "memory");
    asm volatile("barrier.cluster.wait.aligned;" ::: "memory");

    // ldmatrix addressing constants
    const int arow = lane & 15;
    const uint32_t abase = (uint32_t)(arow * 256);
    const int achx = (lane & 16) ? 1 : 0, arx = arow & 7;
    const int nrl = 8 * warp + (lane & 7);   // n-row within 64-col gate block
    const int kc = lane >> 3;                // 0..3 (k8-chunk within k32 group)

    int cur = 0;
    for (int t = 0; t < T_; t++) {
        // prefetch next gx + flags (overlaps MMA)
        float ngx[2][3][2];
        int nf[2]; nf[0] = 0; nf[1] = 0;
        if (t + 1 < T_) {
            #pragma unroll
            for (int bi = 0; bi < 2; bi++) {
                size_t ib = (size_t)(b0 + bA + 8 * bi) * T_ + (t + 1);
                nf[bi] = wm ? (ii32[ib] != 0u) : (ii8[ib] != 0);
                #pragma unroll
                for (int g = 0; g < 3; g++) {
                    float2 gv = *(const float2*)&g_gates[ib * G3 + g * 128 + j_g];
                    ngx[bi][g][0] = gv.x; ngx[bi][g][1] = gv.y;
                }
            }
        }

        // ---- MMA: r,z,n for this rank's 64 columns (8 per warp), 16 batches ----
        float acc[3][4];
        #pragma unroll
        for (int g = 0; g < 3; g++) {
            acc[g][0] = bv[g][0]; acc[g][1] = bv[g][1];
            acc[g][2] = bv[g][0]; acc[g][3] = bv[g][1];
        }
        const uint32_t ahb = aab + (uint32_t)cur * 8192;
        const uint32_t alb = ahb + 4096;
        #pragma unroll
        for (int kk = 0; kk < 4; kk++) {
            uint32_t ah4[2][4], al4[2][4];
            #pragma unroll
            for (int s = 0; s < 2; s++) {
                int k0 = 2 * kk + s;
                uint32_t ach = (uint32_t)((2 * k0 + achx) ^ arx);
                ldsm_x4(ah4[s], ahb + abase + (ach << 4));
                ldsm_x4(al4[s], alb + abase + (ach << 4));
            }
            #pragma unroll
            for (int g = 0; g < 3; g++) {
                int row_local = (g << 6) + nrl;
                uint32_t chunk = (uint32_t)((4 * kk + kc) ^ (lane & 7));
                uint32_t boff = (uint32_t)(row_local * 256) + (chunk << 4);
                uint32_t bh4[4], bl4[4];
                ldsm_x4(bh4, whb + boff);
                ldsm_x4(bl4, wlb + boff);
                #pragma unroll
                for (int s = 0; s < 2; s++) {
                    mma16816(acc[g], ah4[s], bh4 + 2 * s);
                    mma16816(acc[g], ah4[s], bl4 + 2 * s);
                    mma16816(acc[g], al4[s], bh4 + 2 * s);
                }
            }
        }

        // ---- epilogue: GRU nonlinearity for own columns ----
        const int nxt = cur ^ 1;
        char* AHn = sm + RSM_A + nxt * 8192;
        uint32_t pAHn = aab_peer + (uint32_t)nxt * 8192;
        #pragma unroll
        for (int bi = 0; bi < 2; bi++) {
            int b = bA + 8 * bi;
            float hn_[2];
            #pragma unroll
            for (int q = 0; q < 2; q++) {
                float rr = sigf(gxc[bi][0][q] + acc[0][2 * bi + q]);
                float zz = sigf(gxc[bi][1][q] + acc[1][2 * bi + q]);
                float nn = tanhf_fast(gxc[bi][2][q] + rr * acc[2][2 * bi + q]);
                hn_[q] = (1.f - zz) * nn + zz * hprev[bi][q];
            }
            *(float2*)&g_y[((size_t)(b0 + b) * T_ + t) * HD + j_g] = make_float2(hn_[0], hn_[1]);
            if (t + 1 < T_) {
                float2 he = nf[bi] ? make_float2(0.f, 0.f) : make_float2(hn_[0], hn_[1]);
                hprev[bi][0] = he.x; hprev[bi][1] = he.y;
                stA2_both(AHn, pAHn, b, j_g, he);
            } else {
                *(float2*)&hxout[(size_t)(b0 + b) * HD + j_g] = make_float2(hn_[0], hn_[1]);
            }
        }
        if (t + 1 < T_) {
            #pragma unroll
            for (int bi = 0; bi < 2; bi++)
                #pragma unroll
                for (int g = 0; g < 3; g++) {
                    gxc[bi][g][0] = ngx[bi][g][0];
                    gxc[bi][g][1] = ngx[bi][g][1];
                }
            MBAR_ARRIVE_LOCAL(mbar);
            MBAR_ARRIVE_REMOTE(mbar_peer);
            MBAR_WAIT_CL(mbar, (uint32_t)(t & 1));
        }
        cur = nxt;
    }
}

// ---------------- output projection: HMMA (unchanged, validated) ----------------
#define OSM_AH  0
#define OSM_AL  (128 * ASTR * 2)
#define OSM_BH  (2 * 128 * ASTR * 2)
#define OSM_BL  (OSM_BH + 64 * ASTR * 2)
#define OSM_TOT (OSM_BH + 2 * 64 * ASTR * 2)

__global__ void __launch_bounds__(256, 2) out_kernel(
    const float* __restrict__ Wout, const float* __restrict__ bout,
    float* __restrict__ out)
{
    extern __shared__ char smem[];
    __nv_bfloat16* Ah = (__nv_bfloat16*)(smem + OSM_AH);
    __nv_bfloat16* Al = (__nv_bfloat16*)(smem + OSM_AL);
    __nv_bfloat16* Bh = (__nv_bfloat16*)(smem + OSM_BH);
    __nv_bfloat16* Bl = (__nv_bfloat16*)(smem + OSM_BL);
    const uint32_t a_hi = smem_u32(Ah), a_lo = smem_u32(Al);
    const uint32_t b_hi = smem_u32(Bh), b_lo = smem_u32(Bl);
    const int tid = threadIdx.x, warp = tid >> 5, lane = tid & 31;
    const size_t base = (size_t)blockIdx.x * 128;

    for (int p = tid; p < 128 * 64; p += 256) {
        int row = p >> 6, kp = p & 63;
        float2 v = *(const float2*)&g_y[(base + row) * HD + 2 * kp];
        split2(Ah, Al, row * ASTR + 2 * kp, v.x, v.y);
    }
    for (int p = tid; p < 64 * 64; p += 256) {
        int row = p >> 6, kp = p & 63;
        float2 v = *(const float2*)&Wout[row * HD + 2 * kp];
        split2(Bh, Bl, row * ASTR + 2 * kp, v.x, v.y);
    }
    __syncthreads();

    float acc[8][4];
    #pragma unroll
    for (int j = 0; j < 8; j++) { acc[j][0]=acc[j][1]=acc[j][2]=acc[j][3]=0.f; }

    const int arow = 16 * warp + (lane & 7) + ((lane & 8) ? 8 : 0);
    const int acg  = (lane & 16) ? 8 : 0;
    const uint32_t aoff = (uint32_t)(arow * ASTR + acg) * 2;
    const int nloc = (lane & 7) + ((lane & 16) ? 8 : 0);
    const int bkg  = (lane & 8) ? 8 : 0;
    const uint32_t boff = (uint32_t)(nloc * ASTR + bkg) * 2;
    #pragma unroll
    for (int k0 = 0; k0 < 8; k0++) {
        uint32_t ah[4], al[4];
        ldsm_x4(ah, a_hi + aoff + k0 * 32);
        ldsm_x4(al, a_lo + aoff + k0 * 32);
        #pragma unroll
        for (int jp = 0; jp < 4; jp++) {
            uint32_t bo = boff + (uint32_t)(jp * 16 * ASTR) * 2 + k0 * 32;
            uint32_t bh[4], bl[4];
            ldsm_x4(bh, b_hi + bo);
            ldsm_x4(bl, b_lo + bo);
            mma16816(acc[2*jp],     ah, bh);
            mma16816(acc[2*jp],     ah, bl);
            mma16816(acc[2*jp],     al, bh);
            mma16816(acc[2*jp + 1], ah, bh + 2);
            mma16816(acc[2*jp + 1], ah, bl + 2);
            mma16816(acc[2*jp + 1], al, bh + 2);
        }
    }

    const int r0 = 16 * warp + (lane >> 2), r1 = r0 + 8;
    #pragma unroll
    for (int j = 0; j < 8; j++) {
        int col = 8 * j + 2 * (lane & 3);
        float bv0 = __ldg(&bout[col]), bv1 = __ldg(&bout[col + 1]);
        *(float2*)&out[(base + r0) * OD + col] = make_float2(acc[j][0] + bv0, acc[j][1] + bv1);
        *(float2*)&out[(base + r1) * OD + col] = make_float2(acc[j][2] + bv0, acc[j][3] + bv1);
    }
}

// ---------------- launcher ----------------
extern "C" void kernel_launch(void* const* d_in, const int* in_sizes, int n_in,
                              void* d_out, int out_size)
{
    const float* x    = (const float*)d_in[0];
    const void*  isin = d_in[1];
    const float* hx   = (const float*)d_in[2];
    const float* W1   = (const float*)d_in[3];
    const float* b1   = (const float*)d_in[4];
    const float* g1   = (const float*)d_in[5];
    const float* be1  = (const float*)d_in[6];
    const float* W2   = (const float*)d_in[7];
    const float* b2   = (const float*)d_in[8];
    const float* g2   = (const float*)d_in[9];
    const float* be2  = (const float*)d_in[10];
    const float* Wih  = (const float*)d_in[11];
    const float* Whh  = (const float*)d_in[12];
    const float* bih  = (const float*)d_in[13];
    const float* bhh  = (const float*)d_in[14];
    const float* Wout = (const float*)d_in[15];
    const float* bout = (const float*)d_in[16];
    float* out = (float*)d_out;

    cudaFuncSetAttribute(ff_kernel,  cudaFuncAttributeMaxDynamicSharedMemorySize, SM_TOT);
    cudaFuncSetAttribute(rec_kernel, cudaFuncAttributeMaxDynamicSharedMemorySize, RSM_TOT);
    cudaFuncSetAttribute(out_kernel, cudaFuncAttributeMaxDynamicSharedMemorySize, OSM_TOT);

    detect_kernel<<<1, 256>>>((const unsigned int*)isin);
    ff_kernel<<<BT_ / 128, 256, SM_TOT>>>(x, W1, b1, g1, be1, W2, b2, g2, be2, Wih, bih);
    rec_kernel<<<128, 256, RSM_TOT>>>(hx, Whh, bhh, isin, out + (size_t)BT_ * OD);
    out_kernel<<<BT_ / 128, 256, OSM_TOT>>>(Wout, bout, out);
}